// round 1
// baseline (speedup 1.0000x reference)
#include <cuda_runtime.h>
#include <math.h>
#include <stdint.h>

#define Vv     50257
#define Sdim   2048
#define Hdim   1024
#define H2     2048
#define IN3    3072
#define G4     4096
#define PROBN  (Vv + Sdim)   /* 52305 */

/* ------------------------- device scratch (no allocs) ------------------- */
__device__ float g_logits[Sdim];            // attn logits -> attn weights (in place)
__device__ float g_rho[Sdim];               // normalized rho
__device__ float g_colpart[16][2][H2];      // partial column reductions over enc
__device__ float g_ctx[H2];
__device__ float g_rhoenc[H2];
__device__ float g_lstm_in[IN3];            // [x | selective | attentive]
__device__ float g_gates[G4];
__device__ float g_h1[Hdim];
__device__ float g_c1[Hdim];
__device__ float g_scpart[8][Sdim];         // score_c partials over n-blocks

/* ------------------------- math helpers (fast-math safe) ---------------- */
__device__ __forceinline__ float sigmoid_acc(float x) {
    return 1.0f / (1.0f + expf(-x));
}
__device__ __forceinline__ float tanh_acc(float x) {
    // 1 - 2/(e^{2x}+1): saturates correctly, ~1e-7 rel err even with __expf
    return 1.0f - 2.0f / (expf(2.0f * x) + 1.0f);
}

/* ------------------------- K1: attention logits GEMV -------------------- */
__global__ void k_attn(const float* __restrict__ x, const float* __restrict__ h0,
                       const float* __restrict__ W, const float* __restrict__ b) {
    int row = blockIdx.x;
    int t = threadIdx.x;
    const float4* Wr = (const float4*)(W + (size_t)row * H2);
    float acc = 0.f;
#pragma unroll
    for (int i = 0; i < 2; i++) {
        int f = t + i * 256;                 // 512 float4 per row
        float4 w = Wr[f];
        float4 v;
        if (f < 256) v = ((const float4*)x)[f];
        else         v = ((const float4*)h0)[f - 256];
        acc += w.x * v.x + w.y * v.y + w.z * v.z + w.w * v.w;
    }
    __shared__ float red[256];
    red[t] = acc; __syncthreads();
    for (int s = 128; s > 0; s >>= 1) { if (t < s) red[t] += red[t + s]; __syncthreads(); }
    if (t == 0) g_logits[row] = red[0] + b[row];
}

/* ------------------------- K2: rho mask + normalize --------------------- */
__global__ void k_rho(const int* __restrict__ sent, const float* __restrict__ prev_probs,
                      const int* __restrict__ pw) {
    int t = threadIdx.x;
    int w = pw[0];
    float vals[8];
    float part = 0.f;
#pragma unroll
    for (int i = 0; i < 8; i++) {
        int s = t + i * 256;
        float v = (sent[s] == w) ? prev_probs[Vv + s] : 0.f;
        vals[i] = v; part += v;
    }
    __shared__ float red[256];
    red[t] = part; __syncthreads();
    for (int s = 128; s > 0; s >>= 1) { if (t < s) red[t] += red[t + s]; __syncthreads(); }
    float inv = 1.0f / (red[0] + 1e-9f);
#pragma unroll
    for (int i = 0; i < 8; i++) g_rho[t + i * 256] = vals[i] * inv;
}

/* ------------------------- K3: softmax over attn logits ------------------ */
__global__ void k_softmax_attn() {
    int t = threadIdx.x;
    float vals[8];
    float m = -1e30f;
#pragma unroll
    for (int i = 0; i < 8; i++) { vals[i] = g_logits[t + i * 256]; m = fmaxf(m, vals[i]); }
    __shared__ float red[256];
    red[t] = m; __syncthreads();
    for (int s = 128; s > 0; s >>= 1) { if (t < s) red[t] = fmaxf(red[t], red[t + s]); __syncthreads(); }
    m = red[0]; __syncthreads();
    float sum = 0.f;
#pragma unroll
    for (int i = 0; i < 8; i++) { vals[i] = __expf(vals[i] - m); sum += vals[i]; }
    red[t] = sum; __syncthreads();
    for (int s = 128; s > 0; s >>= 1) { if (t < s) red[t] += red[t + s]; __syncthreads(); }
    float inv = 1.0f / red[0];
#pragma unroll
    for (int i = 0; i < 8; i++) g_logits[t + i * 256] = vals[i] * inv;
}

/* --------- K4: fused column reductions ctx & rho@enc over encoder -------- */
__global__ void k_colred(const float* __restrict__ enc) {
    int t   = threadIdx.x;
    int col = blockIdx.x * 256 + t;     // 8 blocks over 2048 cols
    int rc  = blockIdx.y;               // 16 row chunks of 128
    __shared__ float aw[128], rw[128];
    if (t < 128) aw[t] = g_logits[rc * 128 + t];
    else         rw[t - 128] = g_rho[rc * 128 + (t - 128)];
    __syncthreads();
    float a = 0.f, r = 0.f;
    const float* base = enc + (size_t)(rc * 128) * H2 + col;
#pragma unroll 8
    for (int i = 0; i < 128; i++) {
        float v = base[(size_t)i * H2];
        a += aw[i] * v;
        r += rw[i] * v;
    }
    g_colpart[rc][0][col] = a;
    g_colpart[rc][1][col] = r;
}

__global__ void k_colfin(const float* __restrict__ x) {
    int col = blockIdx.x * 256 + threadIdx.x;
    float a = 0.f, r = 0.f;
#pragma unroll
    for (int c = 0; c < 16; c++) { a += g_colpart[c][0][col]; r += g_colpart[c][1][col]; }
    g_ctx[col] = a;
    g_rhoenc[col] = r;
    if (col < Hdim) g_lstm_in[col] = x[col];   // lstm_in[0:H] = x
}

/* --------- K5: attentive & selective GEMVs -> lstm_in -------------------- */
__global__ void k_combws(const float* __restrict__ combW, const float* __restrict__ combb,
                         const float* __restrict__ WsW,  const float* __restrict__ Wsb) {
    int row = blockIdx.x;      // 0..2047
    int t = threadIdx.x;
    bool isComb = row < Hdim;
    const float4* W4 = isComb ? (const float4*)(combW + (size_t)row * H2)
                              : (const float4*)(WsW + (size_t)(row - Hdim) * H2);
    const float4* v4 = isComb ? (const float4*)g_ctx : (const float4*)g_rhoenc;
    float acc = 0.f;
#pragma unroll
    for (int i = 0; i < 2; i++) {
        int f = t + i * 256;
        float4 w = W4[f], v = v4[f];
        acc += w.x * v.x + w.y * v.y + w.z * v.z + w.w * v.w;
    }
    __shared__ float red[256];
    red[t] = acc; __syncthreads();
    for (int s = 128; s > 0; s >>= 1) { if (t < s) red[t] += red[t + s]; __syncthreads(); }
    if (t == 0) {
        if (isComb) g_lstm_in[2 * Hdim + row] = red[0] + combb[row];            // attentive
        else        g_lstm_in[Hdim + (row - Hdim)] = red[0] + Wsb[row - Hdim];  // selective
    }
}

/* --------- K6: gate GEMV --------------------------------------------------*/
__global__ void k_gates(const float* __restrict__ h0,
                        const float* __restrict__ Wih, const float* __restrict__ Whh,
                        const float* __restrict__ bih, const float* __restrict__ bhh) {
    int row = blockIdx.x;     // 0..4095
    int t = threadIdx.x;
    const float4* Wi = (const float4*)(Wih + (size_t)row * IN3);
    const float4* Wh = (const float4*)(Whh + (size_t)row * Hdim);
    const float4* li = (const float4*)g_lstm_in;
    const float4* h4 = (const float4*)h0;
    float acc = 0.f;
#pragma unroll
    for (int i = 0; i < 3; i++) {            // 768 float4 of W_ih
        int f = t + i * 256;
        float4 w = Wi[f], v = li[f];
        acc += w.x * v.x + w.y * v.y + w.z * v.z + w.w * v.w;
    }
    {                                        // 256 float4 of W_hh
        float4 w = Wh[t], v = h4[t];
        acc += w.x * v.x + w.y * v.y + w.z * v.z + w.w * v.w;
    }
    __shared__ float red[256];
    red[t] = acc; __syncthreads();
    for (int s = 128; s > 0; s >>= 1) { if (t < s) red[t] += red[t + s]; __syncthreads(); }
    if (t == 0) g_gates[row] = red[0] + bih[row] + bhh[row];
}

/* --------- K7: LSTM elementwise ------------------------------------------ */
__global__ void k_lstm(const float* __restrict__ c0, float* __restrict__ out) {
    int i = blockIdx.x * 256 + threadIdx.x;   // 0..1023
    float gi = g_gates[i];
    float gf = g_gates[Hdim + i];
    float gg = g_gates[2 * Hdim + i];
    float go = g_gates[3 * Hdim + i];
    float c1 = sigmoid_acc(gf) * c0[i] + sigmoid_acc(gi) * tanh_acc(gg);
    float h1 = sigmoid_acc(go) * tanh_acc(c1);
    g_c1[i] = c1; g_h1[i] = h1;
    out[PROBN + i] = h1;
    out[PROBN + Hdim + i] = c1;
}

/* --------- K8: vocab GEMV score_g = h1 @ Wo.T + b (warp per row) ---------- */
__global__ void k_wo(const float* __restrict__ Wo, const float* __restrict__ Wob,
                     float* __restrict__ out) {
    __shared__ float h1s[Hdim];
    int t = threadIdx.x;
    for (int i = t; i < Hdim; i += 256) h1s[i] = g_h1[i];
    __syncthreads();
    int warp = t >> 5, lane = t & 31;
    int row = blockIdx.x * 8 + warp;
    if (row >= Vv) return;
    const float4* Wr = (const float4*)(Wo + (size_t)row * Hdim);
    const float4* hv = (const float4*)h1s;
    float acc = 0.f;
#pragma unroll
    for (int i = 0; i < 8; i++) {            // 256 float4 per row / 32 lanes
        int f = lane + i * 32;
        float4 w = Wr[f], v = hv[f];
        acc += w.x * v.x + w.y * v.y + w.z * v.z + w.w * v.w;
    }
    for (int s = 16; s > 0; s >>= 1) acc += __shfl_down_sync(0xffffffffu, acc, s);
    if (lane == 0) out[row] = acc + Wob[row];
}

/* --------- K9: score_c GEMM (S x H, K=2H) fused tanh + dot(h1) ------------ */
/* 128x128 tile, BK=16, 8x8 micro-tile, double-buffered smem.                */
__global__ __launch_bounds__(256, 1)
void k_scorec(const float* __restrict__ enc, const float* __restrict__ Wc,
              const float* __restrict__ Wcb) {
    __shared__ float As[2][16][132];
    __shared__ float Bs[2][16][132];
    __shared__ float h1s[128], bss[128];
    __shared__ float red[128][17];

    const int bm0 = blockIdx.x * 128;   // s rows   (16 blocks)
    const int bn0 = blockIdx.y * 128;   // k cols   (8 blocks)
    const int tid = threadIdx.x;
    const int tx = tid & 15, ty = tid >> 4;

    if (tid < 128) { h1s[tid] = g_h1[bn0 + tid]; bss[tid] = Wcb[bn0 + tid]; }

    const int f0 = tid * 2, f1 = tid * 2 + 1;
    const int m0 = f0 >> 2, kg0 = f0 & 3;
    const int m1 = f1 >> 2, kg1 = f1 & 3;
    const float* pa0 = enc + (size_t)(bm0 + m0) * H2 + kg0 * 4;
    const float* pa1 = enc + (size_t)(bm0 + m1) * H2 + kg1 * 4;
    const float* pb0 = Wc  + (size_t)(bn0 + m0) * H2 + kg0 * 4;
    const float* pb1 = Wc  + (size_t)(bn0 + m1) * H2 + kg1 * 4;

    float acc[8][8];
#pragma unroll
    for (int i = 0; i < 8; i++)
#pragma unroll
        for (int j = 0; j < 8; j++) acc[i][j] = 0.f;

    float4 ra0, ra1, rb0, rb1;
    // prologue: tile 0
    ra0 = *(const float4*)(pa0); ra1 = *(const float4*)(pa1);
    rb0 = *(const float4*)(pb0); rb1 = *(const float4*)(pb1);
    {
        int b = 0;
        As[b][kg0 * 4 + 0][m0] = ra0.x; As[b][kg0 * 4 + 1][m0] = ra0.y;
        As[b][kg0 * 4 + 2][m0] = ra0.z; As[b][kg0 * 4 + 3][m0] = ra0.w;
        As[b][kg1 * 4 + 0][m1] = ra1.x; As[b][kg1 * 4 + 1][m1] = ra1.y;
        As[b][kg1 * 4 + 2][m1] = ra1.z; As[b][kg1 * 4 + 3][m1] = ra1.w;
        Bs[b][kg0 * 4 + 0][m0] = rb0.x; Bs[b][kg0 * 4 + 1][m0] = rb0.y;
        Bs[b][kg0 * 4 + 2][m0] = rb0.z; Bs[b][kg0 * 4 + 3][m0] = rb0.w;
        Bs[b][kg1 * 4 + 0][m1] = rb1.x; Bs[b][kg1 * 4 + 1][m1] = rb1.y;
        Bs[b][kg1 * 4 + 2][m1] = rb1.z; Bs[b][kg1 * 4 + 3][m1] = rb1.w;
    }
    __syncthreads();

    int buf = 0;
    for (int kt = 0; kt < 128; kt++) {
        if (kt < 127) {
            int k0 = (kt + 1) * 16;
            ra0 = *(const float4*)(pa0 + k0); ra1 = *(const float4*)(pa1 + k0);
            rb0 = *(const float4*)(pb0 + k0); rb1 = *(const float4*)(pb1 + k0);
        }
#pragma unroll
        for (int kk = 0; kk < 16; kk++) {
            float4 a0 = *(const float4*)&As[buf][kk][ty * 8];
            float4 a1 = *(const float4*)&As[buf][kk][ty * 8 + 4];
            float4 b0 = *(const float4*)&Bs[buf][kk][tx * 8];
            float4 b1 = *(const float4*)&Bs[buf][kk][tx * 8 + 4];
            float av[8] = {a0.x, a0.y, a0.z, a0.w, a1.x, a1.y, a1.z, a1.w};
            float bv[8] = {b0.x, b0.y, b0.z, b0.w, b1.x, b1.y, b1.z, b1.w};
#pragma unroll
            for (int i = 0; i < 8; i++)
#pragma unroll
                for (int j = 0; j < 8; j++) acc[i][j] += av[i] * bv[j];
        }
        if (kt < 127) {
            int nb = buf ^ 1;
            As[nb][kg0 * 4 + 0][m0] = ra0.x; As[nb][kg0 * 4 + 1][m0] = ra0.y;
            As[nb][kg0 * 4 + 2][m0] = ra0.z; As[nb][kg0 * 4 + 3][m0] = ra0.w;
            As[nb][kg1 * 4 + 0][m1] = ra1.x; As[nb][kg1 * 4 + 1][m1] = ra1.y;
            As[nb][kg1 * 4 + 2][m1] = ra1.z; As[nb][kg1 * 4 + 3][m1] = ra1.w;
            Bs[nb][kg0 * 4 + 0][m0] = rb0.x; Bs[nb][kg0 * 4 + 1][m0] = rb0.y;
            Bs[nb][kg0 * 4 + 2][m0] = rb0.z; Bs[nb][kg0 * 4 + 3][m0] = rb0.w;
            Bs[nb][kg1 * 4 + 0][m1] = rb1.x; Bs[nb][kg1 * 4 + 1][m1] = rb1.y;
            Bs[nb][kg1 * 4 + 2][m1] = rb1.z; Bs[nb][kg1 * 4 + 3][m1] = rb1.w;
        }
        __syncthreads();
        buf ^= 1;
    }

    // epilogue: tanh(acc + b[n]) * h1[n], reduce over n within tile
    float rsum[8];
#pragma unroll
    for (int i = 0; i < 8; i++) rsum[i] = 0.f;
#pragma unroll
    for (int i = 0; i < 8; i++) {
#pragma unroll
        for (int j = 0; j < 8; j++) {
            int nc = tx * 8 + j;
            float v = tanh_acc(acc[i][j] + bss[nc]);
            rsum[i] += v * h1s[nc];
        }
    }
#pragma unroll
    for (int i = 0; i < 8; i++) red[ty * 8 + i][tx] = rsum[i];
    __syncthreads();
    if (tid < 128) {
        float s = 0.f;
#pragma unroll
        for (int c = 0; c < 16; c++) s += red[tid][c];
        g_scpart[blockIdx.y][bm0 + tid] = s;
    }
}

__global__ void k_scfin(float* __restrict__ out) {
    int s = blockIdx.x * 256 + threadIdx.x;
    float a = 0.f;
#pragma unroll
    for (int c = 0; c < 8; c++) a += g_scpart[c][s];
    out[Vv + s] = a;
}

/* --------- K10: final softmax over 52305 scores --------------------------- */
__global__ void k_softmax_out(float* __restrict__ out) {
    int t = threadIdx.x;
    __shared__ float red[1024];
    float m = -1e30f;
    for (int i = t; i < PROBN; i += 1024) m = fmaxf(m, out[i]);
    red[t] = m; __syncthreads();
    for (int s = 512; s > 0; s >>= 1) { if (t < s) red[t] = fmaxf(red[t], red[t + s]); __syncthreads(); }
    m = red[0]; __syncthreads();
    float sum = 0.f;
    for (int i = t; i < PROBN; i += 1024) sum += __expf(out[i] - m);
    red[t] = sum; __syncthreads();
    for (int s = 512; s > 0; s >>= 1) { if (t < s) red[t] += red[t + s]; __syncthreads(); }
    float inv = 1.0f / red[0];
    for (int i = t; i < PROBN; i += 1024) out[i] = __expf(out[i] - m) * inv;
}

/* ------------------------- launcher --------------------------------------- */
extern "C" void kernel_launch(void* const* d_in, const int* in_sizes, int n_in,
                              void* d_out, int out_size) {
    const float* x          = (const float*)d_in[0];
    const float* enc        = (const float*)d_in[1];
    const int*   sent       = (const int*)  d_in[2];
    const float* prev_probs = (const float*)d_in[3];
    const float* h0         = (const float*)d_in[4];
    const float* c0         = (const float*)d_in[5];
    const float* attn_W     = (const float*)d_in[6];
    const float* attn_b     = (const float*)d_in[7];
    const float* comb_W     = (const float*)d_in[8];
    const float* comb_b     = (const float*)d_in[9];
    const float* Ws_W       = (const float*)d_in[10];
    const float* Ws_b       = (const float*)d_in[11];
    const float* Wo_W       = (const float*)d_in[12];
    const float* Wo_b       = (const float*)d_in[13];
    const float* Wc_W       = (const float*)d_in[14];
    const float* Wc_b       = (const float*)d_in[15];
    const float* W_ih       = (const float*)d_in[16];
    const float* W_hh       = (const float*)d_in[17];
    const float* b_ih       = (const float*)d_in[18];
    const float* b_hh       = (const float*)d_in[19];
    const int*   pw         = (const int*)  d_in[20];
    float* out = (float*)d_out;

    k_attn<<<Sdim, 256>>>(x, h0, attn_W, attn_b);
    k_rho<<<1, 256>>>(sent, prev_probs, pw);
    k_softmax_attn<<<1, 256>>>();
    k_colred<<<dim3(8, 16), 256>>>(enc);
    k_colfin<<<8, 256>>>(x);
    k_combws<<<2048, 256>>>(comb_W, comb_b, Ws_W, Ws_b);
    k_gates<<<4096, 256>>>(h0, W_ih, W_hh, b_ih, b_hh);
    k_lstm<<<4, 256>>>(c0, out);
    k_wo<<<(Vv + 7) / 8, 256>>>(Wo_W, Wo_b, out);
    k_scorec<<<dim3(16, 8), 256>>>(enc, Wc_W, Wc_b);
    k_scfin<<<8, 256>>>(out);
    k_softmax_out<<<1, 1024>>>(out);
}

// round 3
// speedup vs baseline: 2.4328x; 2.4328x over previous
#include <cuda_runtime.h>
#include <cuda_bf16.h>
#include <math.h>
#include <stdint.h>

#define Vv     50257
#define Sdim   2048
#define Hdim   1024
#define H2     2048
#define IN3    3072
#define G4     4096
#define PROBN  (Vv + Sdim)   /* 52305 */

/* ------------------------- device scratch (no allocs) ------------------- */
__device__ float g_logits[Sdim];
__device__ float g_rho[Sdim];
__device__ float g_colpart[64][2][H2];
__device__ float g_ctx[H2];
__device__ float g_rhoenc[H2];
__device__ float g_lstm_in[IN3];
__device__ float g_gates[G4];
__device__ float g_h1[Hdim];
__device__ float g_c1[Hdim];
__device__ float g_scpart[8][Sdim];

/* bf16 split buffers for the score_c tensor GEMM */
__device__ __nv_bfloat16 g_ehi[(size_t)Sdim * H2];
__device__ __nv_bfloat16 g_elo[(size_t)Sdim * H2];
__device__ __nv_bfloat16 g_whi[(size_t)Hdim * H2];
__device__ __nv_bfloat16 g_wlo[(size_t)Hdim * H2];

/* ------------------------- math helpers (fast-math safe) ---------------- */
__device__ __forceinline__ float sigmoid_acc(float x) {
    return 1.0f / (1.0f + expf(-x));
}
__device__ __forceinline__ float tanh_acc(float x) {
    return 1.0f - 2.0f / (expf(2.0f * x) + 1.0f);
}

__device__ __forceinline__ uint32_t smem_u32(const void* p) {
    uint32_t a;
    asm("{ .reg .u64 t; cvta.to.shared.u64 t, %1; cvt.u32.u64 %0, t; }" : "=r"(a) : "l"(p));
    return a;
}
#define CP_ASYNC16(daddr, sptr) \
    asm volatile("cp.async.ca.shared.global [%0], [%1], 16;" :: "r"(daddr), "l"(sptr) : "memory")
#define CP_COMMIT() asm volatile("cp.async.commit_group;" ::: "memory")
#define CP_WAIT(N)  asm volatile("cp.async.wait_group %0;" :: "n"(N) : "memory")

__device__ __forceinline__ void mma16816(float* c, const uint32_t* a, const uint32_t* b) {
    asm volatile(
        "mma.sync.aligned.m16n8k16.row.col.f32.bf16.bf16.f32 "
        "{%0,%1,%2,%3}, {%4,%5,%6,%7}, {%8,%9}, {%0,%1,%2,%3};"
        : "+f"(c[0]), "+f"(c[1]), "+f"(c[2]), "+f"(c[3])
        : "r"(a[0]), "r"(a[1]), "r"(a[2]), "r"(a[3]), "r"(b[0]), "r"(b[1]));
}

/* ------------------------- K0: fp32 -> bf16 hi/lo splits ----------------- */
__global__ void k_cvt_enc(const float4* __restrict__ src) {
    int i = blockIdx.x * 256 + threadIdx.x;
    float4 v = src[i];
    __nv_bfloat16 hx = __float2bfloat16(v.x), hy = __float2bfloat16(v.y);
    __nv_bfloat16 hz = __float2bfloat16(v.z), hw = __float2bfloat16(v.w);
    __nv_bfloat16 lx = __float2bfloat16(v.x - __bfloat162float(hx));
    __nv_bfloat16 ly = __float2bfloat16(v.y - __bfloat162float(hy));
    __nv_bfloat16 lz = __float2bfloat16(v.z - __bfloat162float(hz));
    __nv_bfloat16 lw = __float2bfloat16(v.w - __bfloat162float(hw));
    __nv_bfloat162* hi = (__nv_bfloat162*)g_ehi;
    __nv_bfloat162* lo = (__nv_bfloat162*)g_elo;
    hi[i * 2] = __halves2bfloat162(hx, hy); hi[i * 2 + 1] = __halves2bfloat162(hz, hw);
    lo[i * 2] = __halves2bfloat162(lx, ly); lo[i * 2 + 1] = __halves2bfloat162(lz, lw);
}
__global__ void k_cvt_wc(const float4* __restrict__ src) {
    int i = blockIdx.x * 256 + threadIdx.x;
    float4 v = src[i];
    __nv_bfloat16 hx = __float2bfloat16(v.x), hy = __float2bfloat16(v.y);
    __nv_bfloat16 hz = __float2bfloat16(v.z), hw = __float2bfloat16(v.w);
    __nv_bfloat16 lx = __float2bfloat16(v.x - __bfloat162float(hx));
    __nv_bfloat16 ly = __float2bfloat16(v.y - __bfloat162float(hy));
    __nv_bfloat16 lz = __float2bfloat16(v.z - __bfloat162float(hz));
    __nv_bfloat16 lw = __float2bfloat16(v.w - __bfloat162float(hw));
    __nv_bfloat162* hi = (__nv_bfloat162*)g_whi;
    __nv_bfloat162* lo = (__nv_bfloat162*)g_wlo;
    hi[i * 2] = __halves2bfloat162(hx, hy); hi[i * 2 + 1] = __halves2bfloat162(hz, hw);
    lo[i * 2] = __halves2bfloat162(lx, ly); lo[i * 2 + 1] = __halves2bfloat162(lz, lw);
}

/* ------------------------- K1: attention logits GEMV -------------------- */
__global__ void k_attn(const float* __restrict__ x, const float* __restrict__ h0,
                       const float* __restrict__ W, const float* __restrict__ b) {
    int row = blockIdx.x;
    int t = threadIdx.x;
    const float4* Wr = (const float4*)(W + (size_t)row * H2);
    float acc = 0.f;
#pragma unroll
    for (int i = 0; i < 2; i++) {
        int f = t + i * 256;
        float4 w = Wr[f];
        float4 v;
        if (f < 256) v = ((const float4*)x)[f];
        else         v = ((const float4*)h0)[f - 256];
        acc += w.x * v.x + w.y * v.y + w.z * v.z + w.w * v.w;
    }
    __shared__ float red[256];
    red[t] = acc; __syncthreads();
    for (int s = 128; s > 0; s >>= 1) { if (t < s) red[t] += red[t + s]; __syncthreads(); }
    if (t == 0) g_logits[row] = red[0] + b[row];
}

/* ------------------------- K2: rho mask + normalize --------------------- */
__global__ void k_rho(const int* __restrict__ sent, const float* __restrict__ prev_probs,
                      const int* __restrict__ pw) {
    int t = threadIdx.x;
    int w = pw[0];
    float vals[8];
    float part = 0.f;
#pragma unroll
    for (int i = 0; i < 8; i++) {
        int s = t + i * 256;
        float v = (sent[s] == w) ? prev_probs[Vv + s] : 0.f;
        vals[i] = v; part += v;
    }
    __shared__ float red[256];
    red[t] = part; __syncthreads();
    for (int s = 128; s > 0; s >>= 1) { if (t < s) red[t] += red[t + s]; __syncthreads(); }
    float inv = 1.0f / (red[0] + 1e-9f);
#pragma unroll
    for (int i = 0; i < 8; i++) g_rho[t + i * 256] = vals[i] * inv;
}

/* ------------------------- K3: softmax over attn logits ------------------ */
__global__ void k_softmax_attn() {
    int t = threadIdx.x;
    float vals[8];
    float m = -1e30f;
#pragma unroll
    for (int i = 0; i < 8; i++) { vals[i] = g_logits[t + i * 256]; m = fmaxf(m, vals[i]); }
    __shared__ float red[256];
    red[t] = m; __syncthreads();
    for (int s = 128; s > 0; s >>= 1) { if (t < s) red[t] = fmaxf(red[t], red[t + s]); __syncthreads(); }
    m = red[0]; __syncthreads();
    float sum = 0.f;
#pragma unroll
    for (int i = 0; i < 8; i++) { vals[i] = __expf(vals[i] - m); sum += vals[i]; }
    red[t] = sum; __syncthreads();
    for (int s = 128; s > 0; s >>= 1) { if (t < s) red[t] += red[t + s]; __syncthreads(); }
    float inv = 1.0f / red[0];
#pragma unroll
    for (int i = 0; i < 8; i++) g_logits[t + i * 256] = vals[i] * inv;
}

/* --------- K4: fused column reductions ctx & rho@enc over encoder -------- */
__global__ void k_colred(const float* __restrict__ enc) {
    int t   = threadIdx.x;
    int col = blockIdx.x * 256 + t;
    int rc  = blockIdx.y;               // 64 row chunks of 32
    __shared__ float aw[32], rw[32];
    if (t < 32) aw[t] = g_logits[rc * 32 + t];
    else if (t < 64) rw[t - 32] = g_rho[rc * 32 + (t - 32)];
    __syncthreads();
    float a = 0.f, r = 0.f;
    const float* base = enc + (size_t)(rc * 32) * H2 + col;
#pragma unroll
    for (int i = 0; i < 32; i++) {
        float v = base[(size_t)i * H2];
        a += aw[i] * v;
        r += rw[i] * v;
    }
    g_colpart[rc][0][col] = a;
    g_colpart[rc][1][col] = r;
}

__global__ void k_colfin(const float* __restrict__ x) {
    int col = blockIdx.x * 256 + threadIdx.x;
    float a = 0.f, r = 0.f;
#pragma unroll
    for (int c = 0; c < 64; c++) { a += g_colpart[c][0][col]; r += g_colpart[c][1][col]; }
    g_ctx[col] = a;
    g_rhoenc[col] = r;
    if (col < Hdim) g_lstm_in[col] = x[col];
}

/* --------- K5: attentive & selective GEMVs -> lstm_in -------------------- */
__global__ void k_combws(const float* __restrict__ combW, const float* __restrict__ combb,
                         const float* __restrict__ WsW,  const float* __restrict__ Wsb) {
    int row = blockIdx.x;
    int t = threadIdx.x;
    bool isComb = row < Hdim;
    const float4* W4 = isComb ? (const float4*)(combW + (size_t)row * H2)
                              : (const float4*)(WsW + (size_t)(row - Hdim) * H2);
    const float4* v4 = isComb ? (const float4*)g_ctx : (const float4*)g_rhoenc;
    float acc = 0.f;
#pragma unroll
    for (int i = 0; i < 2; i++) {
        int f = t + i * 256;
        float4 w = W4[f], v = v4[f];
        acc += w.x * v.x + w.y * v.y + w.z * v.z + w.w * v.w;
    }
    __shared__ float red[256];
    red[t] = acc; __syncthreads();
    for (int s = 128; s > 0; s >>= 1) { if (t < s) red[t] += red[t + s]; __syncthreads(); }
    if (t == 0) {
        if (isComb) g_lstm_in[2 * Hdim + row] = red[0] + combb[row];
        else        g_lstm_in[Hdim + (row - Hdim)] = red[0] + Wsb[row - Hdim];
    }
}

/* --------- K6: gate GEMV --------------------------------------------------*/
__global__ void k_gates(const float* __restrict__ h0,
                        const float* __restrict__ Wih, const float* __restrict__ Whh,
                        const float* __restrict__ bih, const float* __restrict__ bhh) {
    int row = blockIdx.x;
    int t = threadIdx.x;
    const float4* Wi = (const float4*)(Wih + (size_t)row * IN3);
    const float4* Wh = (const float4*)(Whh + (size_t)row * Hdim);
    const float4* li = (const float4*)g_lstm_in;
    const float4* h4 = (const float4*)h0;
    float acc = 0.f;
#pragma unroll
    for (int i = 0; i < 3; i++) {
        int f = t + i * 256;
        float4 w = Wi[f], v = li[f];
        acc += w.x * v.x + w.y * v.y + w.z * v.z + w.w * v.w;
    }
    {
        float4 w = Wh[t], v = h4[t];
        acc += w.x * v.x + w.y * v.y + w.z * v.z + w.w * v.w;
    }
    __shared__ float red[256];
    red[t] = acc; __syncthreads();
    for (int s = 128; s > 0; s >>= 1) { if (t < s) red[t] += red[t + s]; __syncthreads(); }
    if (t == 0) g_gates[row] = red[0] + bih[row] + bhh[row];
}

/* --------- K7: LSTM elementwise ------------------------------------------ */
__global__ void k_lstm(const float* __restrict__ c0, float* __restrict__ out) {
    int i = blockIdx.x * 256 + threadIdx.x;
    float gi = g_gates[i];
    float gf = g_gates[Hdim + i];
    float gg = g_gates[2 * Hdim + i];
    float go = g_gates[3 * Hdim + i];
    float c1 = sigmoid_acc(gf) * c0[i] + sigmoid_acc(gi) * tanh_acc(gg);
    float h1 = sigmoid_acc(go) * tanh_acc(c1);
    g_c1[i] = c1; g_h1[i] = h1;
    out[PROBN + i] = h1;
    out[PROBN + Hdim + i] = c1;
}

/* --------- K8: vocab GEMV score_g = h1 @ Wo.T + b (warp per row) ---------- */
__global__ void k_wo(const float* __restrict__ Wo, const float* __restrict__ Wob,
                     float* __restrict__ out) {
    __shared__ float h1s[Hdim];
    int t = threadIdx.x;
    for (int i = t; i < Hdim; i += 256) h1s[i] = g_h1[i];
    __syncthreads();
    int warp = t >> 5, lane = t & 31;
    int row = blockIdx.x * 8 + warp;
    if (row >= Vv) return;
    const float4* Wr = (const float4*)(Wo + (size_t)row * Hdim);
    const float4* hv = (const float4*)h1s;
    float acc = 0.f;
#pragma unroll
    for (int i = 0; i < 8; i++) {
        int f = lane + i * 32;
        float4 w = Wr[f], v = hv[f];
        acc += w.x * v.x + w.y * v.y + w.z * v.z + w.w * v.w;
    }
    for (int s = 16; s > 0; s >>= 1) acc += __shfl_down_sync(0xffffffffu, acc, s);
    if (lane == 0) out[row] = acc + Wob[row];
}

/* --------- K9: score_c via mma.sync bf16 split GEMM ----------------------- */
/* D = Ahi.Bhi^T + Ahi.Blo^T + Alo.Bhi^T; tile 128x128, Kc=32 staged via     */
/* cp.async double buffering.  Smem rows padded to 40 bf16 (conflict-free).  */
#define KC 32
#define ROWP 40                       /* bf16 per padded row */
#define ROWB (ROWP * 2)               /* 80 bytes per row */
#define TILE_SB (128 * ROWB)          /* 10240 B per tile */
#define STAGE_SB (4 * TILE_SB)        /* 40960 B per stage */
#define NSTAGES (H2 / KC)             /* 64 */

__global__ __launch_bounds__(256, 1)
void k_scorec_mma(const float* __restrict__ Wcb) {
    extern __shared__ char dynsm[];
    __shared__ float h1s[128], bss[128];
    __shared__ float sred[2][128];

    const int tid = threadIdx.x;
    const int wid = tid >> 5, lane = tid & 31;
    const int warpM = wid & 3, warpN = wid >> 2;
    const int m_base = warpM * 32;
    const int n_base = warpN * 64;
    const int bm0 = blockIdx.x * 128;
    const int bn0 = blockIdx.y * 128;

    const uint32_t smbase = smem_u32(dynsm);

    if (tid < 128) { h1s[tid] = g_h1[bn0 + tid]; bss[tid] = Wcb[bn0 + tid]; }

    const __nv_bfloat16* srcAh = g_ehi + (size_t)bm0 * H2;
    const __nv_bfloat16* srcAl = g_elo + (size_t)bm0 * H2;
    const __nv_bfloat16* srcBh = g_whi + (size_t)bn0 * H2;
    const __nv_bfloat16* srcBl = g_wlo + (size_t)bn0 * H2;

    const int lrow0 = tid >> 2;        /* 0..63 */
    const int lq    = tid & 3;         /* uint4 within 64B rowchunk */

    /* stage loader: 4 tiles x 128 rows x 4 uint4 */
#define LOAD_STAGE(CH, BUF) do {                                               \
        int k0 = (CH) * KC;                                                    \
        uint32_t sb = smbase + (BUF) * STAGE_SB;                               \
        _Pragma("unroll")                                                      \
        for (int i = 0; i < 8; i++) {                                          \
            const __nv_bfloat16* s =                                           \
                (i < 2) ? srcAh : (i < 4) ? srcAl : (i < 6) ? srcBh : srcBl;   \
            int row = lrow0 + 64 * (i & 1);                                    \
            const char* gp = (const char*)(s + (size_t)row * H2 + k0) + lq*16; \
            uint32_t dp = sb + (i >> 1) * TILE_SB + row * ROWB + lq * 16;      \
            CP_ASYNC16(dp, gp);                                                \
        }                                                                      \
        CP_COMMIT();                                                           \
    } while (0)

    float acc[2][8][4];
#pragma unroll
    for (int mi = 0; mi < 2; mi++)
#pragma unroll
        for (int ni = 0; ni < 8; ni++)
#pragma unroll
            for (int r = 0; r < 4; r++) acc[mi][ni][r] = 0.f;

    LOAD_STAGE(0, 0);

    int buf = 0;
    for (int ch = 0; ch < NSTAGES; ch++) {
        if (ch + 1 < NSTAGES) { LOAD_STAGE(ch + 1, buf ^ 1); CP_WAIT(1); }
        else                  { CP_WAIT(0); }
        __syncthreads();

        const uint32_t sb = smbase + buf * STAGE_SB;
        const uint32_t ah_b = sb + 0 * TILE_SB;
        const uint32_t al_b = sb + 1 * TILE_SB;
        const uint32_t bh_b = sb + 2 * TILE_SB;
        const uint32_t bl_b = sb + 3 * TILE_SB;

#pragma unroll
        for (int s = 0; s < 2; s++) {           /* two k16 slices per stage */
            const int ks4 = s * 32;             /* byte offset of slice */
            uint32_t ahf[2][4], alf[2][4], bhf[8][2], blf[8][2];
#pragma unroll
            for (int mi = 0; mi < 2; mi++) {
                uint32_t r0 = (m_base + mi * 16 + (lane >> 2));
                uint32_t off0 = r0 * ROWB + ks4 + (lane & 3) * 4;
                uint32_t off1 = off0 + 8 * ROWB;
                asm volatile("ld.shared.b32 %0, [%1];" : "=r"(ahf[mi][0]) : "r"(ah_b + off0));
                asm volatile("ld.shared.b32 %0, [%1];" : "=r"(ahf[mi][1]) : "r"(ah_b + off1));
                asm volatile("ld.shared.b32 %0, [%1];" : "=r"(ahf[mi][2]) : "r"(ah_b + off0 + 16));
                asm volatile("ld.shared.b32 %0, [%1];" : "=r"(ahf[mi][3]) : "r"(ah_b + off1 + 16));
                asm volatile("ld.shared.b32 %0, [%1];" : "=r"(alf[mi][0]) : "r"(al_b + off0));
                asm volatile("ld.shared.b32 %0, [%1];" : "=r"(alf[mi][1]) : "r"(al_b + off1));
                asm volatile("ld.shared.b32 %0, [%1];" : "=r"(alf[mi][2]) : "r"(al_b + off0 + 16));
                asm volatile("ld.shared.b32 %0, [%1];" : "=r"(alf[mi][3]) : "r"(al_b + off1 + 16));
            }
#pragma unroll
            for (int ni = 0; ni < 8; ni++) {
                uint32_t nr = (n_base + ni * 8 + (lane >> 2));
                uint32_t off0 = nr * ROWB + ks4 + (lane & 3) * 4;
                asm volatile("ld.shared.b32 %0, [%1];" : "=r"(bhf[ni][0]) : "r"(bh_b + off0));
                asm volatile("ld.shared.b32 %0, [%1];" : "=r"(bhf[ni][1]) : "r"(bh_b + off0 + 16));
                asm volatile("ld.shared.b32 %0, [%1];" : "=r"(blf[ni][0]) : "r"(bl_b + off0));
                asm volatile("ld.shared.b32 %0, [%1];" : "=r"(blf[ni][1]) : "r"(bl_b + off0 + 16));
            }
#pragma unroll
            for (int mi = 0; mi < 2; mi++)
#pragma unroll
                for (int ni = 0; ni < 8; ni++) {
                    mma16816(acc[mi][ni], ahf[mi], bhf[ni]);
                    mma16816(acc[mi][ni], ahf[mi], blf[ni]);
                    mma16816(acc[mi][ni], alf[mi], bhf[ni]);
                }
        }
        __syncthreads();
        buf ^= 1;
    }

    /* epilogue: p = sum_n tanh(D + b[n]) * h1[n] per row */
    float p[2][2] = {{0.f, 0.f}, {0.f, 0.f}};
#pragma unroll
    for (int mi = 0; mi < 2; mi++)
#pragma unroll
        for (int ni = 0; ni < 8; ni++) {
            int c0 = n_base + ni * 8 + (lane & 3) * 2;
            int c1 = c0 + 1;
            p[mi][0] += tanh_acc(acc[mi][ni][0] + bss[c0]) * h1s[c0]
                      + tanh_acc(acc[mi][ni][1] + bss[c1]) * h1s[c1];
            p[mi][1] += tanh_acc(acc[mi][ni][2] + bss[c0]) * h1s[c0]
                      + tanh_acc(acc[mi][ni][3] + bss[c1]) * h1s[c1];
        }
#pragma unroll
    for (int mi = 0; mi < 2; mi++)
#pragma unroll
        for (int h = 0; h < 2; h++) {
            float v = p[mi][h];
            v += __shfl_xor_sync(0xffffffffu, v, 1);
            v += __shfl_xor_sync(0xffffffffu, v, 2);
            if ((lane & 3) == 0)
                sred[warpN][m_base + mi * 16 + h * 8 + (lane >> 2)] = v;
        }
    __syncthreads();
    if (tid < 128)
        g_scpart[blockIdx.y][bm0 + tid] = sred[0][tid] + sred[1][tid];
}

__global__ void k_scfin(float* __restrict__ out) {
    int s = blockIdx.x * 256 + threadIdx.x;
    float a = 0.f;
#pragma unroll
    for (int c = 0; c < 8; c++) a += g_scpart[c][s];
    out[Vv + s] = a;
}

/* --------- K10: final softmax over 52305 scores --------------------------- */
__global__ void k_softmax_out(float* __restrict__ out) {
    int t = threadIdx.x;
    __shared__ float red[1024];
    float m = -1e30f;
    for (int i = t; i < PROBN; i += 1024) m = fmaxf(m, out[i]);
    red[t] = m; __syncthreads();
    for (int s = 512; s > 0; s >>= 1) { if (t < s) red[t] = fmaxf(red[t], red[t + s]); __syncthreads(); }
    m = red[0]; __syncthreads();
    float sum = 0.f;
    for (int i = t; i < PROBN; i += 1024) sum += __expf(out[i] - m);
    red[t] = sum; __syncthreads();
    for (int s = 512; s > 0; s >>= 1) { if (t < s) red[t] += red[t + s]; __syncthreads(); }
    float inv = 1.0f / red[0];
    for (int i = t; i < PROBN; i += 1024) out[i] = __expf(out[i] - m) * inv;
}

/* ------------------------- launcher --------------------------------------- */
extern "C" void kernel_launch(void* const* d_in, const int* in_sizes, int n_in,
                              void* d_out, int out_size) {
    const float* x          = (const float*)d_in[0];
    const float* enc        = (const float*)d_in[1];
    const int*   sent       = (const int*)  d_in[2];
    const float* prev_probs = (const float*)d_in[3];
    const float* h0         = (const float*)d_in[4];
    const float* c0         = (const float*)d_in[5];
    const float* attn_W     = (const float*)d_in[6];
    const float* attn_b     = (const float*)d_in[7];
    const float* comb_W     = (const float*)d_in[8];
    const float* comb_b     = (const float*)d_in[9];
    const float* Ws_W       = (const float*)d_in[10];
    const float* Ws_b       = (const float*)d_in[11];
    const float* Wo_W       = (const float*)d_in[12];
    const float* Wo_b       = (const float*)d_in[13];
    const float* Wc_W       = (const float*)d_in[14];
    const float* Wc_b       = (const float*)d_in[15];
    const float* W_ih       = (const float*)d_in[16];
    const float* W_hh       = (const float*)d_in[17];
    const float* b_ih       = (const float*)d_in[18];
    const float* b_hh       = (const float*)d_in[19];
    const int*   pw         = (const int*)  d_in[20];
    float* out = (float*)d_out;

    static bool attr_done = false;
    if (!attr_done) {
        cudaFuncSetAttribute(k_scorec_mma, cudaFuncAttributeMaxDynamicSharedMemorySize,
                             2 * STAGE_SB);
        attr_done = true;
    }

    k_cvt_enc<<<4096, 256>>>((const float4*)enc);
    k_cvt_wc<<<2048, 256>>>((const float4*)Wc_W);
    k_attn<<<Sdim, 256>>>(x, h0, attn_W, attn_b);
    k_rho<<<1, 256>>>(sent, prev_probs, pw);
    k_softmax_attn<<<1, 256>>>();
    k_colred<<<dim3(8, 64), 256>>>(enc);
    k_colfin<<<8, 256>>>(x);
    k_combws<<<2048, 256>>>(comb_W, comb_b, Ws_W, Ws_b);
    k_gates<<<4096, 256>>>(h0, W_ih, W_hh, b_ih, b_hh);
    k_lstm<<<4, 256>>>(c0, out);
    k_wo<<<(Vv + 7) / 8, 256>>>(Wo_W, Wo_b, out);
    k_scorec_mma<<<dim3(16, 8), 256, 2 * STAGE_SB>>>(Wc_b);
    k_scfin<<<8, 256>>>(out);
    k_softmax_out<<<1, 1024>>>(out);
}

// round 4
// speedup vs baseline: 3.0386x; 1.2490x over previous
#include <cuda_runtime.h>
#include <cuda_bf16.h>
#include <math.h>
#include <stdint.h>

#define Vv     50257
#define Sdim   2048
#define Hdim   1024
#define H2     2048
#define IN3    3072
#define G4     4096
#define PROBN  (Vv + Sdim)   /* 52305 */

/* ------------------------- device scratch (no allocs) ------------------- */
__device__ float g_logits[Sdim];
__device__ float g_rho[Sdim];
__device__ float g_colpart[64][2][H2];
__device__ float g_ctx[H2];
__device__ float g_rhoenc[H2];
__device__ float g_lstm_in[IN3];
__device__ float g_gates[G4];
__device__ float g_h1[Hdim];
__device__ float g_c1[Hdim];
__device__ float g_scpart[8][Sdim];

/* bf16 split buffers for the score_c tensor GEMM */
__device__ __nv_bfloat16 g_ehi[(size_t)Sdim * H2];
__device__ __nv_bfloat16 g_elo[(size_t)Sdim * H2];
__device__ __nv_bfloat16 g_whi[(size_t)Hdim * H2];
__device__ __nv_bfloat16 g_wlo[(size_t)Hdim * H2];

/* ------------------------- math helpers (fast-math safe) ---------------- */
__device__ __forceinline__ float sigmoid_acc(float x) {
    return 1.0f / (1.0f + expf(-x));
}
__device__ __forceinline__ float tanh_acc(float x) {
    return 1.0f - 2.0f / (expf(2.0f * x) + 1.0f);
}

__device__ __forceinline__ uint32_t smem_u32(const void* p) {
    uint32_t a;
    asm("{ .reg .u64 t; cvta.to.shared.u64 t, %1; cvt.u32.u64 %0, t; }" : "=r"(a) : "l"(p));
    return a;
}
#define CP_ASYNC16(daddr, sptr) \
    asm volatile("cp.async.ca.shared.global [%0], [%1], 16;" :: "r"(daddr), "l"(sptr) : "memory")
#define CP_COMMIT() asm volatile("cp.async.commit_group;" ::: "memory")
#define CP_WAIT(N)  asm volatile("cp.async.wait_group %0;" :: "n"(N) : "memory")

__device__ __forceinline__ void mma16816(float* c, const uint32_t* a, const uint32_t* b) {
    asm volatile(
        "mma.sync.aligned.m16n8k16.row.col.f32.bf16.bf16.f32 "
        "{%0,%1,%2,%3}, {%4,%5,%6,%7}, {%8,%9}, {%0,%1,%2,%3};"
        : "+f"(c[0]), "+f"(c[1]), "+f"(c[2]), "+f"(c[3])
        : "r"(a[0]), "r"(a[1]), "r"(a[2]), "r"(a[3]), "r"(b[0]), "r"(b[1]));
}
__device__ __forceinline__ void ldmx4(uint32_t* r, uint32_t addr) {
    asm volatile("ldmatrix.sync.aligned.m8n8.x4.shared.b16 {%0,%1,%2,%3}, [%4];"
        : "=r"(r[0]), "=r"(r[1]), "=r"(r[2]), "=r"(r[3]) : "r"(addr));
}

/* ------------------------- K0: fp32 -> bf16 hi/lo splits ----------------- */
__global__ void k_cvt_enc(const float4* __restrict__ src) {
    int i = blockIdx.x * 256 + threadIdx.x;
    float4 v = src[i];
    __nv_bfloat16 hx = __float2bfloat16(v.x), hy = __float2bfloat16(v.y);
    __nv_bfloat16 hz = __float2bfloat16(v.z), hw = __float2bfloat16(v.w);
    __nv_bfloat16 lx = __float2bfloat16(v.x - __bfloat162float(hx));
    __nv_bfloat16 ly = __float2bfloat16(v.y - __bfloat162float(hy));
    __nv_bfloat16 lz = __float2bfloat16(v.z - __bfloat162float(hz));
    __nv_bfloat16 lw = __float2bfloat16(v.w - __bfloat162float(hw));
    __nv_bfloat162* hi = (__nv_bfloat162*)g_ehi;
    __nv_bfloat162* lo = (__nv_bfloat162*)g_elo;
    hi[i * 2] = __halves2bfloat162(hx, hy); hi[i * 2 + 1] = __halves2bfloat162(hz, hw);
    lo[i * 2] = __halves2bfloat162(lx, ly); lo[i * 2 + 1] = __halves2bfloat162(lz, lw);
}
__global__ void k_cvt_wc(const float4* __restrict__ src) {
    int i = blockIdx.x * 256 + threadIdx.x;
    float4 v = src[i];
    __nv_bfloat16 hx = __float2bfloat16(v.x), hy = __float2bfloat16(v.y);
    __nv_bfloat16 hz = __float2bfloat16(v.z), hw = __float2bfloat16(v.w);
    __nv_bfloat16 lx = __float2bfloat16(v.x - __bfloat162float(hx));
    __nv_bfloat16 ly = __float2bfloat16(v.y - __bfloat162float(hy));
    __nv_bfloat16 lz = __float2bfloat16(v.z - __bfloat162float(hz));
    __nv_bfloat16 lw = __float2bfloat16(v.w - __bfloat162float(hw));
    __nv_bfloat162* hi = (__nv_bfloat162*)g_whi;
    __nv_bfloat162* lo = (__nv_bfloat162*)g_wlo;
    hi[i * 2] = __halves2bfloat162(hx, hy); hi[i * 2 + 1] = __halves2bfloat162(hz, hw);
    lo[i * 2] = __halves2bfloat162(lx, ly); lo[i * 2 + 1] = __halves2bfloat162(lz, lw);
}

/* ------------------------- K1: attention logits GEMV -------------------- */
__global__ void k_attn(const float* __restrict__ x, const float* __restrict__ h0,
                       const float* __restrict__ W, const float* __restrict__ b) {
    int row = blockIdx.x;
    int t = threadIdx.x;
    const float4* Wr = (const float4*)(W + (size_t)row * H2);
    float acc = 0.f;
#pragma unroll
    for (int i = 0; i < 2; i++) {
        int f = t + i * 256;
        float4 w = Wr[f];
        float4 v;
        if (f < 256) v = ((const float4*)x)[f];
        else         v = ((const float4*)h0)[f - 256];
        acc += w.x * v.x + w.y * v.y + w.z * v.z + w.w * v.w;
    }
    __shared__ float red[256];
    red[t] = acc; __syncthreads();
    for (int s = 128; s > 0; s >>= 1) { if (t < s) red[t] += red[t + s]; __syncthreads(); }
    if (t == 0) g_logits[row] = red[0] + b[row];
}

/* --------------- K2: rho mask+normalize fused with attn softmax ---------- */
__global__ void k_rho_softmax(const int* __restrict__ sent, const float* __restrict__ prev_probs,
                              const int* __restrict__ pw) {
    int t = threadIdx.x;
    __shared__ float red[256];
    /* rho */
    {
        int w = pw[0];
        float vals[8];
        float part = 0.f;
#pragma unroll
        for (int i = 0; i < 8; i++) {
            int s = t + i * 256;
            float v = (sent[s] == w) ? prev_probs[Vv + s] : 0.f;
            vals[i] = v; part += v;
        }
        red[t] = part; __syncthreads();
        for (int s = 128; s > 0; s >>= 1) { if (t < s) red[t] += red[t + s]; __syncthreads(); }
        float inv = 1.0f / (red[0] + 1e-9f);
#pragma unroll
        for (int i = 0; i < 8; i++) g_rho[t + i * 256] = vals[i] * inv;
        __syncthreads();
    }
    /* softmax over attn logits */
    {
        float vals[8];
        float m = -1e30f;
#pragma unroll
        for (int i = 0; i < 8; i++) { vals[i] = g_logits[t + i * 256]; m = fmaxf(m, vals[i]); }
        red[t] = m; __syncthreads();
        for (int s = 128; s > 0; s >>= 1) { if (t < s) red[t] = fmaxf(red[t], red[t + s]); __syncthreads(); }
        m = red[0]; __syncthreads();
        float sum = 0.f;
#pragma unroll
        for (int i = 0; i < 8; i++) { vals[i] = __expf(vals[i] - m); sum += vals[i]; }
        red[t] = sum; __syncthreads();
        for (int s = 128; s > 0; s >>= 1) { if (t < s) red[t] += red[t + s]; __syncthreads(); }
        float inv = 1.0f / red[0];
#pragma unroll
        for (int i = 0; i < 8; i++) g_logits[t + i * 256] = vals[i] * inv;
    }
}

/* --------- K4: fused column reductions ctx & rho@enc over encoder -------- */
__global__ void k_colred(const float* __restrict__ enc) {
    int t   = threadIdx.x;
    int col = blockIdx.x * 256 + t;
    int rc  = blockIdx.y;               // 64 row chunks of 32
    __shared__ float aw[32], rw[32];
    if (t < 32) aw[t] = g_logits[rc * 32 + t];
    else if (t < 64) rw[t - 32] = g_rho[rc * 32 + (t - 32)];
    __syncthreads();
    float a = 0.f, r = 0.f;
    const float* base = enc + (size_t)(rc * 32) * H2 + col;
#pragma unroll
    for (int i = 0; i < 32; i++) {
        float v = base[(size_t)i * H2];
        a += aw[i] * v;
        r += rw[i] * v;
    }
    g_colpart[rc][0][col] = a;
    g_colpart[rc][1][col] = r;
}

__global__ void k_colfin() {
    int col = blockIdx.x * 256 + threadIdx.x;
    float a = 0.f, r = 0.f;
#pragma unroll
    for (int c = 0; c < 64; c++) { a += g_colpart[c][0][col]; r += g_colpart[c][1][col]; }
    g_ctx[col] = a;
    g_rhoenc[col] = r;
}

/* --------- K5: attentive & selective GEMVs -> lstm_in -------------------- */
__global__ void k_combws(const float* __restrict__ combW, const float* __restrict__ combb,
                         const float* __restrict__ WsW,  const float* __restrict__ Wsb) {
    int row = blockIdx.x;
    int t = threadIdx.x;
    bool isComb = row < Hdim;
    const float4* W4 = isComb ? (const float4*)(combW + (size_t)row * H2)
                              : (const float4*)(WsW + (size_t)(row - Hdim) * H2);
    const float4* v4 = isComb ? (const float4*)g_ctx : (const float4*)g_rhoenc;
    float acc = 0.f;
#pragma unroll
    for (int i = 0; i < 2; i++) {
        int f = t + i * 256;
        float4 w = W4[f], v = v4[f];
        acc += w.x * v.x + w.y * v.y + w.z * v.z + w.w * v.w;
    }
    __shared__ float red[256];
    red[t] = acc; __syncthreads();
    for (int s = 128; s > 0; s >>= 1) { if (t < s) red[t] += red[t + s]; __syncthreads(); }
    if (t == 0) {
        if (isComb) g_lstm_in[2 * Hdim + row] = red[0] + combb[row];
        else        g_lstm_in[Hdim + (row - Hdim)] = red[0] + Wsb[row - Hdim];
    }
}

/* --------- K6a: gate GEMV pre-part (x + h0 terms; runs early) ------------ */
__global__ void k_gates_pre(const float* __restrict__ x, const float* __restrict__ h0,
                            const float* __restrict__ Wih, const float* __restrict__ Whh,
                            const float* __restrict__ bih, const float* __restrict__ bhh) {
    int row = blockIdx.x;
    int t = threadIdx.x;
    const float4* Wi = (const float4*)(Wih + (size_t)row * IN3);      /* cols 0:1024 */
    const float4* Wh = (const float4*)(Whh + (size_t)row * Hdim);
    const float4* x4 = (const float4*)x;
    const float4* h4 = (const float4*)h0;
    float acc = 0.f;
    {
        float4 w = Wi[t], v = x4[t];
        acc += w.x * v.x + w.y * v.y + w.z * v.z + w.w * v.w;
    }
    {
        float4 w = Wh[t], v = h4[t];
        acc += w.x * v.x + w.y * v.y + w.z * v.z + w.w * v.w;
    }
    __shared__ float red[256];
    red[t] = acc; __syncthreads();
    for (int s = 128; s > 0; s >>= 1) { if (t < s) red[t] += red[t + s]; __syncthreads(); }
    if (t == 0) g_gates[row] = red[0] + bih[row] + bhh[row];
}

/* --------- K6b: gate GEMV post-part (selective+attentive terms) ---------- */
__global__ void k_gates_post(const float* __restrict__ Wih) {
    int row = blockIdx.x;
    int t = threadIdx.x;
    const float4* Wi = (const float4*)(Wih + (size_t)row * IN3 + Hdim);  /* cols 1024:3072 */
    const float4* li = (const float4*)(g_lstm_in + Hdim);
    float acc = 0.f;
#pragma unroll
    for (int i = 0; i < 2; i++) {
        int f = t + i * 256;
        float4 w = Wi[f], v = li[f];
        acc += w.x * v.x + w.y * v.y + w.z * v.z + w.w * v.w;
    }
    __shared__ float red[256];
    red[t] = acc; __syncthreads();
    for (int s = 128; s > 0; s >>= 1) { if (t < s) red[t] += red[t + s]; __syncthreads(); }
    if (t == 0) g_gates[row] += red[0];
}

/* --------- K7: LSTM elementwise ------------------------------------------ */
__global__ void k_lstm(const float* __restrict__ c0, float* __restrict__ out) {
    int i = blockIdx.x * 256 + threadIdx.x;
    float gi = g_gates[i];
    float gf = g_gates[Hdim + i];
    float gg = g_gates[2 * Hdim + i];
    float go = g_gates[3 * Hdim + i];
    float c1 = sigmoid_acc(gf) * c0[i] + sigmoid_acc(gi) * tanh_acc(gg);
    float h1 = sigmoid_acc(go) * tanh_acc(c1);
    g_c1[i] = c1; g_h1[i] = h1;
    out[PROBN + i] = h1;
    out[PROBN + Hdim + i] = c1;
}

/* --------- K8: vocab GEMV score_g = h1 @ Wo.T + b (warp per row) ---------- */
__global__ void k_wo(const float* __restrict__ Wo, const float* __restrict__ Wob,
                     float* __restrict__ out) {
    __shared__ float h1s[Hdim];
    int t = threadIdx.x;
    for (int i = t; i < Hdim; i += 256) h1s[i] = g_h1[i];
    __syncthreads();
    int warp = t >> 5, lane = t & 31;
    int row = blockIdx.x * 8 + warp;
    if (row >= Vv) return;
    const float4* Wr = (const float4*)(Wo + (size_t)row * Hdim);
    const float4* hv = (const float4*)h1s;
    float acc = 0.f;
#pragma unroll
    for (int i = 0; i < 8; i++) {
        int f = lane + i * 32;
        float4 w = Wr[f], v = hv[f];
        acc += w.x * v.x + w.y * v.y + w.z * v.z + w.w * v.w;
    }
    for (int s = 16; s > 0; s >>= 1) acc += __shfl_down_sync(0xffffffffu, acc, s);
    if (lane == 0) out[row] = acc + Wob[row];
}

/* --------- K9: score_c via mma.sync bf16 split GEMM + ldmatrix ------------ */
#define KC 32
#define ROWP 40                       /* bf16 per padded row */
#define ROWB (ROWP * 2)               /* 80 bytes per row */
#define TILE_SB (128 * ROWB)          /* 10240 B per tile */
#define STAGE_SB (4 * TILE_SB)        /* 40960 B per stage */
#define NSTAGES (H2 / KC)             /* 64 */

__global__ __launch_bounds__(256, 1)
void k_scorec_mma(const float* __restrict__ Wcb) {
    extern __shared__ char dynsm[];
    __shared__ float h1s[128], bss[128];
    __shared__ float sred[2][128];

    const int tid = threadIdx.x;
    const int wid = tid >> 5, lane = tid & 31;
    const int warpM = wid & 3, warpN = wid >> 2;
    const int m_base = warpM * 32;
    const int n_base = warpN * 64;
    const int bm0 = blockIdx.x * 128;
    const int bn0 = blockIdx.y * 128;

    const uint32_t smbase = smem_u32(dynsm);

    if (tid < 128) { h1s[tid] = g_h1[bn0 + tid]; bss[tid] = Wcb[bn0 + tid]; }

    const __nv_bfloat16* srcAh = g_ehi + (size_t)bm0 * H2;
    const __nv_bfloat16* srcAl = g_elo + (size_t)bm0 * H2;
    const __nv_bfloat16* srcBh = g_whi + (size_t)bn0 * H2;
    const __nv_bfloat16* srcBl = g_wlo + (size_t)bn0 * H2;

    const int lrow0 = tid >> 2;        /* 0..63 */
    const int lq    = tid & 3;         /* uint4 within 64B rowchunk */

#define LOAD_STAGE(CH, BUF) do {                                               \
        int k0 = (CH) * KC;                                                    \
        uint32_t sb = smbase + (BUF) * STAGE_SB;                               \
        _Pragma("unroll")                                                      \
        for (int i = 0; i < 8; i++) {                                          \
            const __nv_bfloat16* s =                                           \
                (i < 2) ? srcAh : (i < 4) ? srcAl : (i < 6) ? srcBh : srcBl;   \
            int row = lrow0 + 64 * (i & 1);                                    \
            const char* gp = (const char*)(s + (size_t)row * H2 + k0) + lq*16; \
            uint32_t dp = sb + (i >> 1) * TILE_SB + row * ROWB + lq * 16;      \
            CP_ASYNC16(dp, gp);                                                \
        }                                                                      \
        CP_COMMIT();                                                           \
    } while (0)

    float acc[2][8][4];
#pragma unroll
    for (int mi = 0; mi < 2; mi++)
#pragma unroll
        for (int ni = 0; ni < 8; ni++)
#pragma unroll
            for (int r = 0; r < 4; r++) acc[mi][ni][r] = 0.f;

    LOAD_STAGE(0, 0);

    int buf = 0;
    for (int ch = 0; ch < NSTAGES; ch++) {
        if (ch + 1 < NSTAGES) { LOAD_STAGE(ch + 1, buf ^ 1); CP_WAIT(1); }
        else                  { CP_WAIT(0); }
        __syncthreads();

        const uint32_t sb = smbase + buf * STAGE_SB;
        const uint32_t ah_b = sb + 0 * TILE_SB;
        const uint32_t bh_b = sb + 2 * TILE_SB;

#pragma unroll
        for (int s = 0; s < 2; s++) {           /* two k16 slices per stage */
            const int ks4 = s * 32;             /* byte offset of slice */
            uint32_t ah[2][4], al[2][4], bh[4][4], bl[4][4];
#pragma unroll
            for (int mi = 0; mi < 2; mi++) {
                uint32_t row = m_base + mi * 16 + (lane & 15);
                uint32_t addr = ah_b + row * ROWB + ks4 + ((lane >> 4) << 4);
                ldmx4(ah[mi], addr);
                ldmx4(al[mi], addr + TILE_SB);
            }
#pragma unroll
            for (int p = 0; p < 4; p++) {
                uint32_t row = n_base + p * 16 + ((lane >> 4) << 3) + (lane & 7);
                uint32_t addr = bh_b + row * ROWB + ks4 + (((lane >> 3) & 1) << 4);
                ldmx4(bh[p], addr);
                ldmx4(bl[p], addr + TILE_SB);
            }
#pragma unroll
            for (int mi = 0; mi < 2; mi++)
#pragma unroll
                for (int ni = 0; ni < 8; ni++) {
                    const uint32_t* bhf = &bh[ni >> 1][(ni & 1) * 2];
                    const uint32_t* blf = &bl[ni >> 1][(ni & 1) * 2];
                    mma16816(acc[mi][ni], ah[mi], bhf);
                    mma16816(acc[mi][ni], ah[mi], blf);
                    mma16816(acc[mi][ni], al[mi], bhf);
                }
        }
        __syncthreads();
        buf ^= 1;
    }

    /* epilogue: p = sum_n tanh(D + b[n]) * h1[n] per row */
    float p[2][2] = {{0.f, 0.f}, {0.f, 0.f}};
#pragma unroll
    for (int mi = 0; mi < 2; mi++)
#pragma unroll
        for (int ni = 0; ni < 8; ni++) {
            int c0 = n_base + ni * 8 + (lane & 3) * 2;
            int c1 = c0 + 1;
            p[mi][0] += tanh_acc(acc[mi][ni][0] + bss[c0]) * h1s[c0]
                      + tanh_acc(acc[mi][ni][1] + bss[c1]) * h1s[c1];
            p[mi][1] += tanh_acc(acc[mi][ni][2] + bss[c0]) * h1s[c0]
                      + tanh_acc(acc[mi][ni][3] + bss[c1]) * h1s[c1];
        }
#pragma unroll
    for (int mi = 0; mi < 2; mi++)
#pragma unroll
        for (int h = 0; h < 2; h++) {
            float v = p[mi][h];
            v += __shfl_xor_sync(0xffffffffu, v, 1);
            v += __shfl_xor_sync(0xffffffffu, v, 2);
            if ((lane & 3) == 0)
                sred[warpN][m_base + mi * 16 + h * 8 + (lane >> 2)] = v;
        }
    __syncthreads();
    if (tid < 128)
        g_scpart[blockIdx.y][bm0 + tid] = sred[0][tid] + sred[1][tid];
}

/* --------- K10: score_c finalize + softmax over 52305 scores -------------- */
__global__ void k_softmax_out(float* __restrict__ out) {
    int t = threadIdx.x;
    __shared__ float red[1024];
    /* fused scfin */
    for (int s = t; s < Sdim; s += 1024) {
        float a = 0.f;
#pragma unroll
        for (int c = 0; c < 8; c++) a += g_scpart[c][s];
        out[Vv + s] = a;
    }
    __syncthreads();
    float m = -1e30f;
    for (int i = t; i < PROBN; i += 1024) m = fmaxf(m, out[i]);
    red[t] = m; __syncthreads();
    for (int s = 512; s > 0; s >>= 1) { if (t < s) red[t] = fmaxf(red[t], red[t + s]); __syncthreads(); }
    m = red[0]; __syncthreads();
    float sum = 0.f;
    for (int i = t; i < PROBN; i += 1024) sum += __expf(out[i] - m);
    red[t] = sum; __syncthreads();
    for (int s = 512; s > 0; s >>= 1) { if (t < s) red[t] += red[t + s]; __syncthreads(); }
    float inv = 1.0f / red[0];
    for (int i = t; i < PROBN; i += 1024) out[i] = __expf(out[i] - m) * inv;
}

/* ------------------------- launcher --------------------------------------- */
extern "C" void kernel_launch(void* const* d_in, const int* in_sizes, int n_in,
                              void* d_out, int out_size) {
    const float* x          = (const float*)d_in[0];
    const float* enc        = (const float*)d_in[1];
    const int*   sent       = (const int*)  d_in[2];
    const float* prev_probs = (const float*)d_in[3];
    const float* h0         = (const float*)d_in[4];
    const float* c0         = (const float*)d_in[5];
    const float* attn_W     = (const float*)d_in[6];
    const float* attn_b     = (const float*)d_in[7];
    const float* comb_W     = (const float*)d_in[8];
    const float* comb_b     = (const float*)d_in[9];
    const float* Ws_W       = (const float*)d_in[10];
    const float* Ws_b       = (const float*)d_in[11];
    const float* Wo_W       = (const float*)d_in[12];
    const float* Wo_b       = (const float*)d_in[13];
    const float* Wc_W       = (const float*)d_in[14];
    const float* Wc_b       = (const float*)d_in[15];
    const float* W_ih       = (const float*)d_in[16];
    const float* W_hh       = (const float*)d_in[17];
    const float* b_ih       = (const float*)d_in[18];
    const float* b_hh       = (const float*)d_in[19];
    const int*   pw         = (const int*)  d_in[20];
    float* out = (float*)d_out;

    cudaFuncSetAttribute(k_scorec_mma, cudaFuncAttributeMaxDynamicSharedMemorySize,
                         2 * STAGE_SB);

    /* one-time side-stream + event setup (host-side resources only) */
    static cudaStream_t s1 = 0;
    static cudaEvent_t e0 = 0, e1 = 0, e2 = 0, e3 = 0;
    static int use_streams = -1;
    if (use_streams < 0) {
        if (cudaStreamCreateWithFlags(&s1, cudaStreamNonBlocking) == cudaSuccess &&
            cudaEventCreateWithFlags(&e0, cudaEventDisableTiming) == cudaSuccess &&
            cudaEventCreateWithFlags(&e1, cudaEventDisableTiming) == cudaSuccess &&
            cudaEventCreateWithFlags(&e2, cudaEventDisableTiming) == cudaSuccess &&
            cudaEventCreateWithFlags(&e3, cudaEventDisableTiming) == cudaSuccess)
            use_streams = 1;
        else
            use_streams = 0;
    }

    if (use_streams) {
        /* fork: side branch does conversions + gate pre-part */
        cudaEventRecord(e0, 0);
        cudaStreamWaitEvent(s1, e0, 0);
        k_cvt_enc<<<4096, 256, 0, s1>>>((const float4*)enc);
        k_cvt_wc<<<2048, 256, 0, s1>>>((const float4*)Wc_W);
        k_gates_pre<<<G4, 256, 0, s1>>>(x, h0, W_ih, W_hh, b_ih, b_hh);
        cudaEventRecord(e1, s1);

        /* main chain */
        k_attn<<<Sdim, 256>>>(x, h0, attn_W, attn_b);
        k_rho_softmax<<<1, 256>>>(sent, prev_probs, pw);
        k_colred<<<dim3(8, 64), 256>>>(enc);
        k_colfin<<<8, 256>>>();
        k_combws<<<2048, 256>>>(comb_W, comb_b, Ws_W, Ws_b);
        cudaStreamWaitEvent(0, e1, 0);         /* need gates_pre + cvts */
        k_gates_post<<<G4, 256>>>(W_ih);
        k_lstm<<<4, 256>>>(c0, out);

        /* fork again: vocab GEMV on side stream, tensor GEMM on main */
        cudaEventRecord(e2, 0);
        cudaStreamWaitEvent(s1, e2, 0);
        k_wo<<<(Vv + 7) / 8, 256, 0, s1>>>(Wo_W, Wo_b, out);
        cudaEventRecord(e3, s1);

        k_scorec_mma<<<dim3(16, 8), 256, 2 * STAGE_SB>>>(Wc_b);
        cudaStreamWaitEvent(0, e3, 0);         /* join before softmax */
        k_softmax_out<<<1, 1024>>>(out);
    } else {
        k_cvt_enc<<<4096, 256>>>((const float4*)enc);
        k_cvt_wc<<<2048, 256>>>((const float4*)Wc_W);
        k_gates_pre<<<G4, 256>>>(x, h0, W_ih, W_hh, b_ih, b_hh);
        k_attn<<<Sdim, 256>>>(x, h0, attn_W, attn_b);
        k_rho_softmax<<<1, 256>>>(sent, prev_probs, pw);
        k_colred<<<dim3(8, 64), 256>>>(enc);
        k_colfin<<<8, 256>>>();
        k_combws<<<2048, 256>>>(comb_W, comb_b, Ws_W, Ws_b);
        k_gates_post<<<G4, 256>>>(W_ih);
        k_lstm<<<4, 256>>>(c0, out);
        k_wo<<<(Vv + 7) / 8, 256>>>(Wo_W, Wo_b, out);
        k_scorec_mma<<<dim3(16, 8), 256, 2 * STAGE_SB>>>(Wc_b);
        k_softmax_out<<<1, 1024>>>(out);
    }
}

// round 5
// speedup vs baseline: 3.0737x; 1.0115x over previous
#include <cuda_runtime.h>
#include <cuda_bf16.h>
#include <math.h>
#include <stdint.h>

#define Vv     50257
#define Sdim   2048
#define Hdim   1024
#define H2     2048
#define IN3    3072
#define G4     4096
#define PROBN  (Vv + Sdim)   /* 52305 */

/* ------------------------- device scratch (no allocs) ------------------- */
__device__ float g_logits[Sdim];
__device__ float g_rho[Sdim];
__device__ float g_colpart[64][2][H2];
__device__ float g_ctx[H2];
__device__ float g_rhoenc[H2];
__device__ float g_lstm_in[IN3];
__device__ float g_gates[G4];
__device__ float g_h1[Hdim];
__device__ float g_c1[Hdim];
__device__ float g_scpart[8][Sdim];

/* bf16 split buffers for the score_c tensor GEMM */
__device__ __nv_bfloat16 g_ehi[(size_t)Sdim * H2];
__device__ __nv_bfloat16 g_elo[(size_t)Sdim * H2];
__device__ __nv_bfloat16 g_whi[(size_t)Hdim * H2];
__device__ __nv_bfloat16 g_wlo[(size_t)Hdim * H2];

/* ------------------------- math helpers (fast-math safe) ---------------- */
__device__ __forceinline__ float sigmoid_acc(float x) {
    return 1.0f / (1.0f + expf(-x));
}
__device__ __forceinline__ float tanh_acc(float x) {
    return 1.0f - 2.0f / (expf(2.0f * x) + 1.0f);
}
__device__ __forceinline__ float dot4(float4 a, float4 b) {
    return a.x * b.x + a.y * b.y + a.z * b.z + a.w * b.w;
}
__device__ __forceinline__ float warp_red(float v) {
#pragma unroll
    for (int s = 16; s > 0; s >>= 1) v += __shfl_down_sync(0xffffffffu, v, s);
    return v;
}

__device__ __forceinline__ uint32_t smem_u32(const void* p) {
    uint32_t a;
    asm("{ .reg .u64 t; cvta.to.shared.u64 t, %1; cvt.u32.u64 %0, t; }" : "=r"(a) : "l"(p));
    return a;
}
#define CP_ASYNC16(daddr, sptr) \
    asm volatile("cp.async.ca.shared.global [%0], [%1], 16;" :: "r"(daddr), "l"(sptr) : "memory")
#define CP_COMMIT() asm volatile("cp.async.commit_group;" ::: "memory")
#define CP_WAIT(N)  asm volatile("cp.async.wait_group %0;" :: "n"(N) : "memory")

__device__ __forceinline__ void mma16816(float* c, const uint32_t* a, const uint32_t* b) {
    asm volatile(
        "mma.sync.aligned.m16n8k16.row.col.f32.bf16.bf16.f32 "
        "{%0,%1,%2,%3}, {%4,%5,%6,%7}, {%8,%9}, {%0,%1,%2,%3};"
        : "+f"(c[0]), "+f"(c[1]), "+f"(c[2]), "+f"(c[3])
        : "r"(a[0]), "r"(a[1]), "r"(a[2]), "r"(a[3]), "r"(b[0]), "r"(b[1]));
}
__device__ __forceinline__ void ldmx4(uint32_t* r, uint32_t addr) {
    asm volatile("ldmatrix.sync.aligned.m8n8.x4.shared.b16 {%0,%1,%2,%3}, [%4];"
        : "=r"(r[0]), "=r"(r[1]), "=r"(r[2]), "=r"(r[3]) : "r"(addr));
}

/* ------------------------- K0: fp32 -> bf16 hi/lo splits ----------------- */
__global__ void k_cvt_enc(const float4* __restrict__ src) {
    int i = blockIdx.x * 256 + threadIdx.x;
    float4 v = src[i];
    __nv_bfloat16 hx = __float2bfloat16(v.x), hy = __float2bfloat16(v.y);
    __nv_bfloat16 hz = __float2bfloat16(v.z), hw = __float2bfloat16(v.w);
    __nv_bfloat16 lx = __float2bfloat16(v.x - __bfloat162float(hx));
    __nv_bfloat16 ly = __float2bfloat16(v.y - __bfloat162float(hy));
    __nv_bfloat16 lz = __float2bfloat16(v.z - __bfloat162float(hz));
    __nv_bfloat16 lw = __float2bfloat16(v.w - __bfloat162float(hw));
    __nv_bfloat162* hi = (__nv_bfloat162*)g_ehi;
    __nv_bfloat162* lo = (__nv_bfloat162*)g_elo;
    hi[i * 2] = __halves2bfloat162(hx, hy); hi[i * 2 + 1] = __halves2bfloat162(hz, hw);
    lo[i * 2] = __halves2bfloat162(lx, ly); lo[i * 2 + 1] = __halves2bfloat162(lz, lw);
}
__global__ void k_cvt_wc(const float4* __restrict__ src) {
    int i = blockIdx.x * 256 + threadIdx.x;
    float4 v = src[i];
    __nv_bfloat16 hx = __float2bfloat16(v.x), hy = __float2bfloat16(v.y);
    __nv_bfloat16 hz = __float2bfloat16(v.z), hw = __float2bfloat16(v.w);
    __nv_bfloat16 lx = __float2bfloat16(v.x - __bfloat162float(hx));
    __nv_bfloat16 ly = __float2bfloat16(v.y - __bfloat162float(hy));
    __nv_bfloat16 lz = __float2bfloat16(v.z - __bfloat162float(hz));
    __nv_bfloat16 lw = __float2bfloat16(v.w - __bfloat162float(hw));
    __nv_bfloat162* hi = (__nv_bfloat162*)g_whi;
    __nv_bfloat162* lo = (__nv_bfloat162*)g_wlo;
    hi[i * 2] = __halves2bfloat162(hx, hy); hi[i * 2 + 1] = __halves2bfloat162(hz, hw);
    lo[i * 2] = __halves2bfloat162(lx, ly); lo[i * 2 + 1] = __halves2bfloat162(lz, lw);
}

/* ------------- K1: attention logits GEMV (warp per row, 8 rows/blk) ------ */
__global__ void k_attn(const float* __restrict__ x, const float* __restrict__ h0,
                       const float* __restrict__ W, const float* __restrict__ b) {
    __shared__ float4 vec[512];
    int t = threadIdx.x;
    vec[t]       = ((const float4*)x)[t & 255];
    if (t < 256) vec[t] = ((const float4*)x)[t];
    else         vec[t] = ((const float4*)h0)[t - 256];
    vec[t + 256 < 512 ? t + 256 : t] = vec[t + 256 < 512 ? t + 256 : t]; /* no-op guard */
    /* simpler: 256 threads each fill two slots */
    __syncthreads();
    if (t < 256) { vec[t] = ((const float4*)x)[t]; vec[t + 256] = ((const float4*)h0)[t]; }
    __syncthreads();
    int warp = t >> 5, lane = t & 31;
    int row = blockIdx.x * 8 + warp;
    const float4* Wr = (const float4*)(W + (size_t)row * H2);
    float acc = 0.f;
#pragma unroll
    for (int i = 0; i < 16; i++) {
        int f = lane + i * 32;
        acc += dot4(Wr[f], vec[f]);
    }
    acc = warp_red(acc);
    if (lane == 0) g_logits[row] = acc + b[row];
}

/* --------------- K2: rho mask+normalize fused with attn softmax ---------- */
__global__ void k_rho_softmax(const int* __restrict__ sent, const float* __restrict__ prev_probs,
                              const int* __restrict__ pw) {
    int t = threadIdx.x;
    __shared__ float red[256];
    {
        int w = pw[0];
        float vals[8];
        float part = 0.f;
#pragma unroll
        for (int i = 0; i < 8; i++) {
            int s = t + i * 256;
            float v = (sent[s] == w) ? prev_probs[Vv + s] : 0.f;
            vals[i] = v; part += v;
        }
        red[t] = part; __syncthreads();
        for (int s = 128; s > 0; s >>= 1) { if (t < s) red[t] += red[t + s]; __syncthreads(); }
        float inv = 1.0f / (red[0] + 1e-9f);
#pragma unroll
        for (int i = 0; i < 8; i++) g_rho[t + i * 256] = vals[i] * inv;
        __syncthreads();
    }
    {
        float vals[8];
        float m = -1e30f;
#pragma unroll
        for (int i = 0; i < 8; i++) { vals[i] = g_logits[t + i * 256]; m = fmaxf(m, vals[i]); }
        red[t] = m; __syncthreads();
        for (int s = 128; s > 0; s >>= 1) { if (t < s) red[t] = fmaxf(red[t], red[t + s]); __syncthreads(); }
        m = red[0]; __syncthreads();
        float sum = 0.f;
#pragma unroll
        for (int i = 0; i < 8; i++) { vals[i] = __expf(vals[i] - m); sum += vals[i]; }
        red[t] = sum; __syncthreads();
        for (int s = 128; s > 0; s >>= 1) { if (t < s) red[t] += red[t + s]; __syncthreads(); }
        float inv = 1.0f / red[0];
#pragma unroll
        for (int i = 0; i < 8; i++) g_logits[t + i * 256] = vals[i] * inv;
    }
}

/* --------- K4: fused column reductions ctx & rho@enc over encoder -------- */
__global__ void k_colred(const float* __restrict__ enc) {
    int t   = threadIdx.x;
    int col = blockIdx.x * 256 + t;
    int rc  = blockIdx.y;               // 64 row chunks of 32
    __shared__ float aw[32], rw[32];
    if (t < 32) aw[t] = g_logits[rc * 32 + t];
    else if (t < 64) rw[t - 32] = g_rho[rc * 32 + (t - 32)];
    __syncthreads();
    float a = 0.f, r = 0.f;
    const float* base = enc + (size_t)(rc * 32) * H2 + col;
#pragma unroll
    for (int i = 0; i < 32; i++) {
        float v = base[(size_t)i * H2];
        a += aw[i] * v;
        r += rw[i] * v;
    }
    g_colpart[rc][0][col] = a;
    g_colpart[rc][1][col] = r;
}

__global__ void k_colfin() {
    int col = blockIdx.x * 256 + threadIdx.x;
    float a = 0.f, r = 0.f;
#pragma unroll
    for (int c = 0; c < 64; c++) { a += g_colpart[c][0][col]; r += g_colpart[c][1][col]; }
    g_ctx[col] = a;
    g_rhoenc[col] = r;
}

/* -------- K5: attentive & selective GEMVs (warp per row, 8/blk) ---------- */
__global__ void k_combws(const float* __restrict__ combW, const float* __restrict__ combb,
                         const float* __restrict__ WsW,  const float* __restrict__ Wsb) {
    __shared__ float4 vec[512];
    int t = threadIdx.x;
    bool isComb = blockIdx.x < 128;
    const float4* v4 = isComb ? (const float4*)g_ctx : (const float4*)g_rhoenc;
    if (t < 256) { vec[t] = v4[t]; vec[t + 256] = v4[t + 256]; }
    __syncthreads();
    int warp = t >> 5, lane = t & 31;
    int row = blockIdx.x * 8 + warp;     /* 0..2047 */
    int lrow = isComb ? row : row - Hdim;
    const float4* Wr = isComb ? (const float4*)(combW + (size_t)lrow * H2)
                              : (const float4*)(WsW + (size_t)lrow * H2);
    float acc = 0.f;
#pragma unroll
    for (int i = 0; i < 16; i++) {
        int f = lane + i * 32;
        acc += dot4(Wr[f], vec[f]);
    }
    acc = warp_red(acc);
    if (lane == 0) {
        if (isComb) g_lstm_in[2 * Hdim + lrow] = acc + combb[lrow];
        else        g_lstm_in[Hdim + lrow] = acc + Wsb[lrow];
    }
}

/* --------- K6a: gate GEMV pre-part (x + h0 terms; warp per row) ---------- */
__global__ void k_gates_pre(const float* __restrict__ x, const float* __restrict__ h0,
                            const float* __restrict__ Wih, const float* __restrict__ Whh,
                            const float* __restrict__ bih, const float* __restrict__ bhh) {
    __shared__ float4 vx[256], vh[256];
    int t = threadIdx.x;
    if (t < 256) { vx[t] = ((const float4*)x)[t]; vh[t] = ((const float4*)h0)[t]; }
    __syncthreads();
    int warp = t >> 5, lane = t & 31;
    int row = blockIdx.x * 8 + warp;     /* 0..4095 */
    const float4* Wi = (const float4*)(Wih + (size_t)row * IN3);
    const float4* Wh = (const float4*)(Whh + (size_t)row * Hdim);
    float acc = 0.f;
#pragma unroll
    for (int i = 0; i < 8; i++) {
        int f = lane + i * 32;
        acc += dot4(Wi[f], vx[f]);
        acc += dot4(Wh[f], vh[f]);
    }
    acc = warp_red(acc);
    if (lane == 0) g_gates[row] = acc + bih[row] + bhh[row];
}

/* --------- K6b: gate GEMV post-part (selective+attentive; warp/row) ------ */
__global__ void k_gates_post(const float* __restrict__ Wih) {
    __shared__ float4 vec[512];
    int t = threadIdx.x;
    const float4* li = (const float4*)(g_lstm_in + Hdim);
    if (t < 256) { vec[t] = li[t]; vec[t + 256] = li[t + 256]; }
    __syncthreads();
    int warp = t >> 5, lane = t & 31;
    int row = blockIdx.x * 8 + warp;
    const float4* Wi = (const float4*)(Wih + (size_t)row * IN3 + Hdim);
    float acc = 0.f;
#pragma unroll
    for (int i = 0; i < 16; i++) {
        int f = lane + i * 32;
        acc += dot4(Wi[f], vec[f]);
    }
    acc = warp_red(acc);
    if (lane == 0) g_gates[row] += acc;
}

/* --------- K7: LSTM elementwise ------------------------------------------ */
__global__ void k_lstm(const float* __restrict__ c0, float* __restrict__ out) {
    int i = blockIdx.x * 256 + threadIdx.x;
    float gi = g_gates[i];
    float gf = g_gates[Hdim + i];
    float gg = g_gates[2 * Hdim + i];
    float go = g_gates[3 * Hdim + i];
    float c1 = sigmoid_acc(gf) * c0[i] + sigmoid_acc(gi) * tanh_acc(gg);
    float h1 = sigmoid_acc(go) * tanh_acc(c1);
    g_c1[i] = c1; g_h1[i] = h1;
    out[PROBN + i] = h1;
    out[PROBN + Hdim + i] = c1;
}

/* --------- K8: vocab GEMV score_g = h1 @ Wo.T + b (warp per row) ---------- */
__global__ void k_wo(const float* __restrict__ Wo, const float* __restrict__ Wob,
                     float* __restrict__ out) {
    __shared__ float h1s[Hdim];
    int t = threadIdx.x;
    for (int i = t; i < Hdim; i += 256) h1s[i] = g_h1[i];
    __syncthreads();
    int warp = t >> 5, lane = t & 31;
    int row = blockIdx.x * 8 + warp;
    if (row >= Vv) return;
    const float4* Wr = (const float4*)(Wo + (size_t)row * Hdim);
    const float4* hv = (const float4*)h1s;
    float acc = 0.f;
#pragma unroll
    for (int i = 0; i < 8; i++) {
        int f = lane + i * 32;
        acc += dot4(Wr[f], hv[f]);
    }
    acc = warp_red(acc);
    if (lane == 0) out[row] = acc + Wob[row];
}

/* --------- K9: score_c via mma.sync bf16 split GEMM + ldmatrix ------------ */
#define KC 32
#define ROWP 40                       /* bf16 per padded row */
#define ROWB (ROWP * 2)               /* 80 bytes per row */
#define TILE_SB (128 * ROWB)          /* 10240 B per tile */
#define STAGE_SB (4 * TILE_SB)        /* 40960 B per stage */
#define NPIPE 4
#define NSTAGES (H2 / KC)             /* 64 */

__global__ __launch_bounds__(256, 1)
void k_scorec_mma(const float* __restrict__ Wcb) {
    extern __shared__ char dynsm[];
    __shared__ float h1s[128], bss[128];
    __shared__ float sred[2][128];

    const int tid = threadIdx.x;
    const int wid = tid >> 5, lane = tid & 31;
    const int warpM = wid & 3, warpN = wid >> 2;
    const int m_base = warpM * 32;
    const int n_base = warpN * 64;
    const int bm0 = blockIdx.x * 128;
    const int bn0 = blockIdx.y * 128;

    const uint32_t smbase = smem_u32(dynsm);

    if (tid < 128) { h1s[tid] = g_h1[bn0 + tid]; bss[tid] = Wcb[bn0 + tid]; }

    const __nv_bfloat16* srcAh = g_ehi + (size_t)bm0 * H2;
    const __nv_bfloat16* srcAl = g_elo + (size_t)bm0 * H2;
    const __nv_bfloat16* srcBh = g_whi + (size_t)bn0 * H2;
    const __nv_bfloat16* srcBl = g_wlo + (size_t)bn0 * H2;

    const int lrow0 = tid >> 2;        /* 0..63 */
    const int lq    = tid & 3;         /* uint4 within 64B rowchunk */

#define LOAD_STAGE(CH, BUF) do {                                               \
        int k0 = (CH) * KC;                                                    \
        uint32_t sb = smbase + (BUF) * STAGE_SB;                               \
        _Pragma("unroll")                                                      \
        for (int i = 0; i < 8; i++) {                                          \
            const __nv_bfloat16* s =                                           \
                (i < 2) ? srcAh : (i < 4) ? srcAl : (i < 6) ? srcBh : srcBl;   \
            int row = lrow0 + 64 * (i & 1);                                    \
            const char* gp = (const char*)(s + (size_t)row * H2 + k0) + lq*16; \
            uint32_t dp = sb + (i >> 1) * TILE_SB + row * ROWB + lq * 16;      \
            CP_ASYNC16(dp, gp);                                                \
        }                                                                      \
        CP_COMMIT();                                                           \
    } while (0)

    float acc[2][8][4];
#pragma unroll
    for (int mi = 0; mi < 2; mi++)
#pragma unroll
        for (int ni = 0; ni < 8; ni++)
#pragma unroll
            for (int r = 0; r < 4; r++) acc[mi][ni][r] = 0.f;

    LOAD_STAGE(0, 0);
    LOAD_STAGE(1, 1);
    LOAD_STAGE(2, 2);

    for (int ch = 0; ch < NSTAGES; ch++) {
        if (ch + 3 < NSTAGES)      { LOAD_STAGE(ch + 3, (ch + 3) & 3); CP_WAIT(3); }
        else if (ch + 2 < NSTAGES) { CP_WAIT(2); }
        else if (ch + 1 < NSTAGES) { CP_WAIT(1); }
        else                       { CP_WAIT(0); }
        __syncthreads();

        const uint32_t sb = smbase + (ch & 3) * STAGE_SB;
        const uint32_t ah_b = sb + 0 * TILE_SB;
        const uint32_t bh_b = sb + 2 * TILE_SB;

#pragma unroll
        for (int s = 0; s < 2; s++) {           /* two k16 slices per stage */
            const int ks4 = s * 32;             /* byte offset of slice */
            uint32_t ah[2][4], al[2][4], bh[4][4], bl[4][4];
#pragma unroll
            for (int mi = 0; mi < 2; mi++) {
                uint32_t row = m_base + mi * 16 + (lane & 15);
                uint32_t addr = ah_b + row * ROWB + ks4 + ((lane >> 4) << 4);
                ldmx4(ah[mi], addr);
                ldmx4(al[mi], addr + TILE_SB);
            }
#pragma unroll
            for (int p = 0; p < 4; p++) {
                uint32_t row = n_base + p * 16 + ((lane >> 4) << 3) + (lane & 7);
                uint32_t addr = bh_b + row * ROWB + ks4 + (((lane >> 3) & 1) << 4);
                ldmx4(bh[p], addr);
                ldmx4(bl[p], addr + TILE_SB);
            }
#pragma unroll
            for (int mi = 0; mi < 2; mi++)
#pragma unroll
                for (int ni = 0; ni < 8; ni++) {
                    const uint32_t* bhf = &bh[ni >> 1][(ni & 1) * 2];
                    const uint32_t* blf = &bl[ni >> 1][(ni & 1) * 2];
                    mma16816(acc[mi][ni], ah[mi], bhf);
                    mma16816(acc[mi][ni], ah[mi], blf);
                    mma16816(acc[mi][ni], al[mi], bhf);
                }
        }
        __syncthreads();
    }

    /* epilogue: p = sum_n tanh(D + b[n]) * h1[n] per row */
    float p[2][2] = {{0.f, 0.f}, {0.f, 0.f}};
#pragma unroll
    for (int mi = 0; mi < 2; mi++)
#pragma unroll
        for (int ni = 0; ni < 8; ni++) {
            int c0 = n_base + ni * 8 + (lane & 3) * 2;
            int c1 = c0 + 1;
            p[mi][0] += tanh_acc(acc[mi][ni][0] + bss[c0]) * h1s[c0]
                      + tanh_acc(acc[mi][ni][1] + bss[c1]) * h1s[c1];
            p[mi][1] += tanh_acc(acc[mi][ni][2] + bss[c0]) * h1s[c0]
                      + tanh_acc(acc[mi][ni][3] + bss[c1]) * h1s[c1];
        }
#pragma unroll
    for (int mi = 0; mi < 2; mi++)
#pragma unroll
        for (int h = 0; h < 2; h++) {
            float v = p[mi][h];
            v += __shfl_xor_sync(0xffffffffu, v, 1);
            v += __shfl_xor_sync(0xffffffffu, v, 2);
            if ((lane & 3) == 0)
                sred[warpN][m_base + mi * 16 + h * 8 + (lane >> 2)] = v;
        }
    __syncthreads();
    if (tid < 128)
        g_scpart[blockIdx.y][bm0 + tid] = sred[0][tid] + sred[1][tid];
}

/* --------- K10: score_c finalize + softmax over 52305 scores -------------- */
__global__ void k_softmax_out(float* __restrict__ out) {
    int t = threadIdx.x;
    __shared__ float red[1024];
    for (int s = t; s < Sdim; s += 1024) {
        float a = 0.f;
#pragma unroll
        for (int c = 0; c < 8; c++) a += g_scpart[c][s];
        out[Vv + s] = a;
    }
    __syncthreads();
    float m = -1e30f;
    for (int i = t; i < PROBN; i += 1024) m = fmaxf(m, out[i]);
    red[t] = m; __syncthreads();
    for (int s = 512; s > 0; s >>= 1) { if (t < s) red[t] = fmaxf(red[t], red[t + s]); __syncthreads(); }
    m = red[0]; __syncthreads();
    float sum = 0.f;
    for (int i = t; i < PROBN; i += 1024) sum += __expf(out[i] - m);
    red[t] = sum; __syncthreads();
    for (int s = 512; s > 0; s >>= 1) { if (t < s) red[t] += red[t + s]; __syncthreads(); }
    float inv = 1.0f / red[0];
    for (int i = t; i < PROBN; i += 1024) out[i] = __expf(out[i] - m) * inv;
}

/* ------------------------- launcher --------------------------------------- */
extern "C" void kernel_launch(void* const* d_in, const int* in_sizes, int n_in,
                              void* d_out, int out_size) {
    const float* x          = (const float*)d_in[0];
    const float* enc        = (const float*)d_in[1];
    const int*   sent       = (const int*)  d_in[2];
    const float* prev_probs = (const float*)d_in[3];
    const float* h0         = (const float*)d_in[4];
    const float* c0         = (const float*)d_in[5];
    const float* attn_W     = (const float*)d_in[6];
    const float* attn_b     = (const float*)d_in[7];
    const float* comb_W     = (const float*)d_in[8];
    const float* comb_b     = (const float*)d_in[9];
    const float* Ws_W       = (const float*)d_in[10];
    const float* Ws_b       = (const float*)d_in[11];
    const float* Wo_W       = (const float*)d_in[12];
    const float* Wo_b       = (const float*)d_in[13];
    const float* Wc_W       = (const float*)d_in[14];
    const float* Wc_b       = (const float*)d_in[15];
    const float* W_ih       = (const float*)d_in[16];
    const float* W_hh       = (const float*)d_in[17];
    const float* b_ih       = (const float*)d_in[18];
    const float* b_hh       = (const float*)d_in[19];
    const int*   pw         = (const int*)  d_in[20];
    float* out = (float*)d_out;

    cudaFuncSetAttribute(k_scorec_mma, cudaFuncAttributeMaxDynamicSharedMemorySize,
                         NPIPE * STAGE_SB);

    static cudaStream_t s1 = 0;
    static cudaEvent_t e0 = 0, e1 = 0, e2 = 0, e3 = 0;
    static int use_streams = -1;
    if (use_streams < 0) {
        if (cudaStreamCreateWithFlags(&s1, cudaStreamNonBlocking) == cudaSuccess &&
            cudaEventCreateWithFlags(&e0, cudaEventDisableTiming) == cudaSuccess &&
            cudaEventCreateWithFlags(&e1, cudaEventDisableTiming) == cudaSuccess &&
            cudaEventCreateWithFlags(&e2, cudaEventDisableTiming) == cudaSuccess &&
            cudaEventCreateWithFlags(&e3, cudaEventDisableTiming) == cudaSuccess)
            use_streams = 1;
        else
            use_streams = 0;
    }

    if (use_streams) {
        cudaEventRecord(e0, 0);
        cudaStreamWaitEvent(s1, e0, 0);
        k_cvt_enc<<<4096, 256, 0, s1>>>((const float4*)enc);
        k_cvt_wc<<<2048, 256, 0, s1>>>((const float4*)Wc_W);
        k_gates_pre<<<512, 256, 0, s1>>>(x, h0, W_ih, W_hh, b_ih, b_hh);
        cudaEventRecord(e1, s1);

        k_attn<<<256, 256>>>(x, h0, attn_W, attn_b);
        k_rho_softmax<<<1, 256>>>(sent, prev_probs, pw);
        k_colred<<<dim3(8, 64), 256>>>(enc);
        k_colfin<<<8, 256>>>();
        k_combws<<<256, 256>>>(comb_W, comb_b, Ws_W, Ws_b);
        cudaStreamWaitEvent(0, e1, 0);
        k_gates_post<<<512, 256>>>(W_ih);
        k_lstm<<<4, 256>>>(c0, out);

        cudaEventRecord(e2, 0);
        cudaStreamWaitEvent(s1, e2, 0);
        k_wo<<<(Vv + 7) / 8, 256, 0, s1>>>(Wo_W, Wo_b, out);
        cudaEventRecord(e3, s1);

        k_scorec_mma<<<dim3(16, 8), 256, NPIPE * STAGE_SB>>>(Wc_b);
        cudaStreamWaitEvent(0, e3, 0);
        k_softmax_out<<<1, 1024>>>(out);
    } else {
        k_cvt_enc<<<4096, 256>>>((const float4*)enc);
        k_cvt_wc<<<2048, 256>>>((const float4*)Wc_W);
        k_gates_pre<<<512, 256>>>(x, h0, W_ih, W_hh, b_ih, b_hh);
        k_attn<<<256, 256>>>(x, h0, attn_W, attn_b);
        k_rho_softmax<<<1, 256>>>(sent, prev_probs, pw);
        k_colred<<<dim3(8, 64), 256>>>(enc);
        k_colfin<<<8, 256>>>();
        k_combws<<<256, 256>>>(comb_W, comb_b, Ws_W, Ws_b);
        k_gates_post<<<512, 256>>>(W_ih);
        k_lstm<<<4, 256>>>(c0, out);
        k_wo<<<(Vv + 7) / 8, 256>>>(Wo_W, Wo_b, out);
        k_scorec_mma<<<dim3(16, 8), 256, NPIPE * STAGE_SB>>>(Wc_b);
        k_softmax_out<<<1, 1024>>>(out);
    }
}

// round 6
// speedup vs baseline: 3.3388x; 1.0862x over previous
#include <cuda_runtime.h>
#include <cuda_bf16.h>
#include <math.h>
#include <stdint.h>

#define Vv     50257
#define Sdim   2048
#define Hdim   1024
#define H2     2048
#define IN3    3072
#define G4     4096
#define PROBN  (Vv + Sdim)   /* 52305 */

/* ------------------------- device scratch (no allocs) ------------------- */
__device__ float g_logits[Sdim];
__device__ float g_rho[Sdim];
__device__ float g_colpart[64][2][H2];
__device__ float g_ctx[H2];
__device__ float g_rhoenc[H2];
__device__ float g_lstm_in[IN3];
__device__ float g_gates[G4];
__device__ float g_h1[Hdim];
__device__ float g_c1[Hdim];
__device__ float g_tanh[(size_t)Sdim * Hdim];   /* tanh(enc@Wc.T+b) matrix */

/* bf16 split buffers for the score_c tensor GEMM */
__device__ __nv_bfloat16 g_ehi[(size_t)Sdim * H2];
__device__ __nv_bfloat16 g_elo[(size_t)Sdim * H2];
__device__ __nv_bfloat16 g_whi[(size_t)Hdim * H2];
__device__ __nv_bfloat16 g_wlo[(size_t)Hdim * H2];

/* ------------------------- math helpers (fast-math safe) ---------------- */
__device__ __forceinline__ float sigmoid_acc(float x) {
    return 1.0f / (1.0f + expf(-x));
}
__device__ __forceinline__ float tanh_acc(float x) {
    return 1.0f - 2.0f / (expf(2.0f * x) + 1.0f);
}
__device__ __forceinline__ float dot4(float4 a, float4 b) {
    return a.x * b.x + a.y * b.y + a.z * b.z + a.w * b.w;
}
__device__ __forceinline__ float warp_red(float v) {
#pragma unroll
    for (int s = 16; s > 0; s >>= 1) v += __shfl_down_sync(0xffffffffu, v, s);
    return v;
}

__device__ __forceinline__ uint32_t smem_u32(const void* p) {
    uint32_t a;
    asm("{ .reg .u64 t; cvta.to.shared.u64 t, %1; cvt.u32.u64 %0, t; }" : "=r"(a) : "l"(p));
    return a;
}
#define CP_ASYNC16(daddr, sptr) \
    asm volatile("cp.async.ca.shared.global [%0], [%1], 16;" :: "r"(daddr), "l"(sptr) : "memory")
#define CP_COMMIT() asm volatile("cp.async.commit_group;" ::: "memory")
#define CP_WAIT(N)  asm volatile("cp.async.wait_group %0;" :: "n"(N) : "memory")

__device__ __forceinline__ void mma16816(float* c, const uint32_t* a, const uint32_t* b) {
    asm volatile(
        "mma.sync.aligned.m16n8k16.row.col.f32.bf16.bf16.f32 "
        "{%0,%1,%2,%3}, {%4,%5,%6,%7}, {%8,%9}, {%0,%1,%2,%3};"
        : "+f"(c[0]), "+f"(c[1]), "+f"(c[2]), "+f"(c[3])
        : "r"(a[0]), "r"(a[1]), "r"(a[2]), "r"(a[3]), "r"(b[0]), "r"(b[1]));
}
__device__ __forceinline__ void ldmx4(uint32_t* r, uint32_t addr) {
    asm volatile("ldmatrix.sync.aligned.m8n8.x4.shared.b16 {%0,%1,%2,%3}, [%4];"
        : "=r"(r[0]), "=r"(r[1]), "=r"(r[2]), "=r"(r[3]) : "r"(addr));
}

/* ------------------------- K0: fp32 -> bf16 hi/lo splits ----------------- */
__global__ void k_cvt_enc(const float4* __restrict__ src) {
    int i = blockIdx.x * 256 + threadIdx.x;
    float4 v = src[i];
    __nv_bfloat16 hx = __float2bfloat16(v.x), hy = __float2bfloat16(v.y);
    __nv_bfloat16 hz = __float2bfloat16(v.z), hw = __float2bfloat16(v.w);
    __nv_bfloat16 lx = __float2bfloat16(v.x - __bfloat162float(hx));
    __nv_bfloat16 ly = __float2bfloat16(v.y - __bfloat162float(hy));
    __nv_bfloat16 lz = __float2bfloat16(v.z - __bfloat162float(hz));
    __nv_bfloat16 lw = __float2bfloat16(v.w - __bfloat162float(hw));
    __nv_bfloat162* hi = (__nv_bfloat162*)g_ehi;
    __nv_bfloat162* lo = (__nv_bfloat162*)g_elo;
    hi[i * 2] = __halves2bfloat162(hx, hy); hi[i * 2 + 1] = __halves2bfloat162(hz, hw);
    lo[i * 2] = __halves2bfloat162(lx, ly); lo[i * 2 + 1] = __halves2bfloat162(lz, lw);
}
__global__ void k_cvt_wc(const float4* __restrict__ src) {
    int i = blockIdx.x * 256 + threadIdx.x;
    float4 v = src[i];
    __nv_bfloat16 hx = __float2bfloat16(v.x), hy = __float2bfloat16(v.y);
    __nv_bfloat16 hz = __float2bfloat16(v.z), hw = __float2bfloat16(v.w);
    __nv_bfloat16 lx = __float2bfloat16(v.x - __bfloat162float(hx));
    __nv_bfloat16 ly = __float2bfloat16(v.y - __bfloat162float(hy));
    __nv_bfloat16 lz = __float2bfloat16(v.z - __bfloat162float(hz));
    __nv_bfloat16 lw = __float2bfloat16(v.w - __bfloat162float(hw));
    __nv_bfloat162* hi = (__nv_bfloat162*)g_whi;
    __nv_bfloat162* lo = (__nv_bfloat162*)g_wlo;
    hi[i * 2] = __halves2bfloat162(hx, hy); hi[i * 2 + 1] = __halves2bfloat162(hz, hw);
    lo[i * 2] = __halves2bfloat162(lx, ly); lo[i * 2 + 1] = __halves2bfloat162(lz, lw);
}

/* ------------- K1: attention logits GEMV (warp per row, 8 rows/blk) ------ */
__global__ void k_attn(const float* __restrict__ x, const float* __restrict__ h0,
                       const float* __restrict__ W, const float* __restrict__ b) {
    __shared__ float4 vec[512];
    int t = threadIdx.x;
    if (t < 256) { vec[t] = ((const float4*)x)[t]; vec[t + 256] = ((const float4*)h0)[t]; }
    __syncthreads();
    int warp = t >> 5, lane = t & 31;
    int row = blockIdx.x * 8 + warp;
    const float4* Wr = (const float4*)(W + (size_t)row * H2);
    float acc = 0.f;
#pragma unroll
    for (int i = 0; i < 16; i++) {
        int f = lane + i * 32;
        acc += dot4(Wr[f], vec[f]);
    }
    acc = warp_red(acc);
    if (lane == 0) g_logits[row] = acc + b[row];
}

/* --------------- K2: rho mask+normalize fused with attn softmax ---------- */
__global__ void k_rho_softmax(const int* __restrict__ sent, const float* __restrict__ prev_probs,
                              const int* __restrict__ pw) {
    int t = threadIdx.x;
    __shared__ float red[256];
    {
        int w = pw[0];
        float vals[8];
        float part = 0.f;
#pragma unroll
        for (int i = 0; i < 8; i++) {
            int s = t + i * 256;
            float v = (sent[s] == w) ? prev_probs[Vv + s] : 0.f;
            vals[i] = v; part += v;
        }
        red[t] = part; __syncthreads();
        for (int s = 128; s > 0; s >>= 1) { if (t < s) red[t] += red[t + s]; __syncthreads(); }
        float inv = 1.0f / (red[0] + 1e-9f);
#pragma unroll
        for (int i = 0; i < 8; i++) g_rho[t + i * 256] = vals[i] * inv;
        __syncthreads();
    }
    {
        float vals[8];
        float m = -1e30f;
#pragma unroll
        for (int i = 0; i < 8; i++) { vals[i] = g_logits[t + i * 256]; m = fmaxf(m, vals[i]); }
        red[t] = m; __syncthreads();
        for (int s = 128; s > 0; s >>= 1) { if (t < s) red[t] = fmaxf(red[t], red[t + s]); __syncthreads(); }
        m = red[0]; __syncthreads();
        float sum = 0.f;
#pragma unroll
        for (int i = 0; i < 8; i++) { vals[i] = __expf(vals[i] - m); sum += vals[i]; }
        red[t] = sum; __syncthreads();
        for (int s = 128; s > 0; s >>= 1) { if (t < s) red[t] += red[t + s]; __syncthreads(); }
        float inv = 1.0f / red[0];
#pragma unroll
        for (int i = 0; i < 8; i++) g_logits[t + i * 256] = vals[i] * inv;
    }
}

/* --------- K4: fused column reductions ctx & rho@enc over encoder -------- */
__global__ void k_colred(const float* __restrict__ enc) {
    int t   = threadIdx.x;
    int col = blockIdx.x * 256 + t;
    int rc  = blockIdx.y;               // 64 row chunks of 32
    __shared__ float aw[32], rw[32];
    if (t < 32) aw[t] = g_logits[rc * 32 + t];
    else if (t < 64) rw[t - 32] = g_rho[rc * 32 + (t - 32)];
    __syncthreads();
    float a = 0.f, r = 0.f;
    const float* base = enc + (size_t)(rc * 32) * H2 + col;
#pragma unroll
    for (int i = 0; i < 32; i++) {
        float v = base[(size_t)i * H2];
        a += aw[i] * v;
        r += rw[i] * v;
    }
    g_colpart[rc][0][col] = a;
    g_colpart[rc][1][col] = r;
}

__global__ void k_colfin() {
    int col = blockIdx.x * 256 + threadIdx.x;
    float a = 0.f, r = 0.f;
#pragma unroll
    for (int c = 0; c < 64; c++) { a += g_colpart[c][0][col]; r += g_colpart[c][1][col]; }
    g_ctx[col] = a;
    g_rhoenc[col] = r;
}

/* -------- K5: attentive & selective GEMVs (warp per row, 8/blk) ---------- */
__global__ void k_combws(const float* __restrict__ combW, const float* __restrict__ combb,
                         const float* __restrict__ WsW,  const float* __restrict__ Wsb) {
    __shared__ float4 vec[512];
    int t = threadIdx.x;
    bool isComb = blockIdx.x < 128;
    const float4* v4 = isComb ? (const float4*)g_ctx : (const float4*)g_rhoenc;
    if (t < 256) { vec[t] = v4[t]; vec[t + 256] = v4[t + 256]; }
    __syncthreads();
    int warp = t >> 5, lane = t & 31;
    int row = blockIdx.x * 8 + warp;     /* 0..2047 */
    int lrow = isComb ? row : row - Hdim;
    const float4* Wr = isComb ? (const float4*)(combW + (size_t)lrow * H2)
                              : (const float4*)(WsW + (size_t)lrow * H2);
    float acc = 0.f;
#pragma unroll
    for (int i = 0; i < 16; i++) {
        int f = lane + i * 32;
        acc += dot4(Wr[f], vec[f]);
    }
    acc = warp_red(acc);
    if (lane == 0) {
        if (isComb) g_lstm_in[2 * Hdim + lrow] = acc + combb[lrow];
        else        g_lstm_in[Hdim + lrow] = acc + Wsb[lrow];
    }
}

/* --------- K6a: gate GEMV pre-part (x + h0 terms; warp per row) ---------- */
__global__ void k_gates_pre(const float* __restrict__ x, const float* __restrict__ h0,
                            const float* __restrict__ Wih, const float* __restrict__ Whh,
                            const float* __restrict__ bih, const float* __restrict__ bhh) {
    __shared__ float4 vx[256], vh[256];
    int t = threadIdx.x;
    if (t < 256) { vx[t] = ((const float4*)x)[t]; vh[t] = ((const float4*)h0)[t]; }
    __syncthreads();
    int warp = t >> 5, lane = t & 31;
    int row = blockIdx.x * 8 + warp;     /* 0..4095 */
    const float4* Wi = (const float4*)(Wih + (size_t)row * IN3);
    const float4* Wh = (const float4*)(Whh + (size_t)row * Hdim);
    float acc = 0.f;
#pragma unroll
    for (int i = 0; i < 8; i++) {
        int f = lane + i * 32;
        acc += dot4(Wi[f], vx[f]);
        acc += dot4(Wh[f], vh[f]);
    }
    acc = warp_red(acc);
    if (lane == 0) g_gates[row] = acc + bih[row] + bhh[row];
}

/* --------- K6b: gate GEMV post-part (selective+attentive; warp/row) ------ */
__global__ void k_gates_post(const float* __restrict__ Wih) {
    __shared__ float4 vec[512];
    int t = threadIdx.x;
    const float4* li = (const float4*)(g_lstm_in + Hdim);
    if (t < 256) { vec[t] = li[t]; vec[t + 256] = li[t + 256]; }
    __syncthreads();
    int warp = t >> 5, lane = t & 31;
    int row = blockIdx.x * 8 + warp;
    const float4* Wi = (const float4*)(Wih + (size_t)row * IN3 + Hdim);
    float acc = 0.f;
#pragma unroll
    for (int i = 0; i < 16; i++) {
        int f = lane + i * 32;
        acc += dot4(Wi[f], vec[f]);
    }
    acc = warp_red(acc);
    if (lane == 0) g_gates[row] += acc;
}

/* --------- K7: LSTM elementwise ------------------------------------------ */
__global__ void k_lstm(const float* __restrict__ c0, float* __restrict__ out) {
    int i = blockIdx.x * 256 + threadIdx.x;
    float gi = g_gates[i];
    float gf = g_gates[Hdim + i];
    float gg = g_gates[2 * Hdim + i];
    float go = g_gates[3 * Hdim + i];
    float c1 = sigmoid_acc(gf) * c0[i] + sigmoid_acc(gi) * tanh_acc(gg);
    float h1 = sigmoid_acc(go) * tanh_acc(c1);
    g_c1[i] = c1; g_h1[i] = h1;
    out[PROBN + i] = h1;
    out[PROBN + Hdim + i] = c1;
}

/* --------- K8: vocab GEMV score_g = h1 @ Wo.T + b (warp per row) ---------- */
__global__ void k_wo(const float* __restrict__ Wo, const float* __restrict__ Wob,
                     float* __restrict__ out) {
    __shared__ float h1s[Hdim];
    int t = threadIdx.x;
    for (int i = t; i < Hdim; i += 256) h1s[i] = g_h1[i];
    __syncthreads();
    int warp = t >> 5, lane = t & 31;
    int row = blockIdx.x * 8 + warp;
    if (row >= Vv) return;
    const float4* Wr = (const float4*)(Wo + (size_t)row * Hdim);
    const float4* hv = (const float4*)h1s;
    float acc = 0.f;
#pragma unroll
    for (int i = 0; i < 8; i++) {
        int f = lane + i * 32;
        acc += dot4(Wr[f], hv[f]);
    }
    acc = warp_red(acc);
    if (lane == 0) out[row] = acc + Wob[row];
}

/* --------- K9: tanh(enc@Wc.T+b) matrix via mma.sync bf16 split GEMM ------ */
/* h1-independent: runs concurrently with the whole LSTM chain.             */
#define KC 32
#define ROWP 40                       /* bf16 per padded row */
#define ROWB (ROWP * 2)               /* 80 bytes per row */
#define TILE_SB (128 * ROWB)          /* 10240 B per tile */
#define STAGE_SB (4 * TILE_SB)        /* 40960 B per stage */
#define NPIPE 4
#define NSTAGES (H2 / KC)             /* 64 */

__global__ __launch_bounds__(256, 1)
void k_scorec_mma(const float* __restrict__ Wcb) {
    extern __shared__ char dynsm[];
    __shared__ float bss[128];

    const int tid = threadIdx.x;
    const int wid = tid >> 5, lane = tid & 31;
    const int warpM = wid & 3, warpN = wid >> 2;
    const int m_base = warpM * 32;
    const int n_base = warpN * 64;
    const int bm0 = blockIdx.x * 128;
    const int bn0 = blockIdx.y * 128;

    const uint32_t smbase = smem_u32(dynsm);

    if (tid < 128) bss[tid] = Wcb[bn0 + tid];

    const __nv_bfloat16* srcAh = g_ehi + (size_t)bm0 * H2;
    const __nv_bfloat16* srcAl = g_elo + (size_t)bm0 * H2;
    const __nv_bfloat16* srcBh = g_whi + (size_t)bn0 * H2;
    const __nv_bfloat16* srcBl = g_wlo + (size_t)bn0 * H2;

    const int lrow0 = tid >> 2;        /* 0..63 */
    const int lq    = tid & 3;         /* uint4 within 64B rowchunk */

#define LOAD_STAGE(CH, BUF) do {                                               \
        int k0 = (CH) * KC;                                                    \
        uint32_t sb = smbase + (BUF) * STAGE_SB;                               \
        _Pragma("unroll")                                                      \
        for (int i = 0; i < 8; i++) {                                          \
            const __nv_bfloat16* s =                                           \
                (i < 2) ? srcAh : (i < 4) ? srcAl : (i < 6) ? srcBh : srcBl;   \
            int row = lrow0 + 64 * (i & 1);                                    \
            const char* gp = (const char*)(s + (size_t)row * H2 + k0) + lq*16; \
            uint32_t dp = sb + (i >> 1) * TILE_SB + row * ROWB + lq * 16;      \
            CP_ASYNC16(dp, gp);                                                \
        }                                                                      \
        CP_COMMIT();                                                           \
    } while (0)

    float acc[2][8][4];
#pragma unroll
    for (int mi = 0; mi < 2; mi++)
#pragma unroll
        for (int ni = 0; ni < 8; ni++)
#pragma unroll
            for (int r = 0; r < 4; r++) acc[mi][ni][r] = 0.f;

    LOAD_STAGE(0, 0);
    LOAD_STAGE(1, 1);
    LOAD_STAGE(2, 2);

    for (int ch = 0; ch < NSTAGES; ch++) {
        if (ch + 3 < NSTAGES)      { LOAD_STAGE(ch + 3, (ch + 3) & 3); CP_WAIT(3); }
        else if (ch + 2 < NSTAGES) { CP_WAIT(2); }
        else if (ch + 1 < NSTAGES) { CP_WAIT(1); }
        else                       { CP_WAIT(0); }
        __syncthreads();

        const uint32_t sb = smbase + (ch & 3) * STAGE_SB;
        const uint32_t ah_b = sb + 0 * TILE_SB;
        const uint32_t bh_b = sb + 2 * TILE_SB;

#pragma unroll
        for (int s = 0; s < 2; s++) {           /* two k16 slices per stage */
            const int ks4 = s * 32;             /* byte offset of slice */
            uint32_t ah[2][4], al[2][4], bh[4][4], bl[4][4];
#pragma unroll
            for (int mi = 0; mi < 2; mi++) {
                uint32_t row = m_base + mi * 16 + (lane & 15);
                uint32_t addr = ah_b + row * ROWB + ks4 + ((lane >> 4) << 4);
                ldmx4(ah[mi], addr);
                ldmx4(al[mi], addr + TILE_SB);
            }
#pragma unroll
            for (int p = 0; p < 4; p++) {
                uint32_t row = n_base + p * 16 + ((lane >> 4) << 3) + (lane & 7);
                uint32_t addr = bh_b + row * ROWB + ks4 + (((lane >> 3) & 1) << 4);
                ldmx4(bh[p], addr);
                ldmx4(bl[p], addr + TILE_SB);
            }
#pragma unroll
            for (int mi = 0; mi < 2; mi++)
#pragma unroll
                for (int ni = 0; ni < 8; ni++) {
                    const uint32_t* bhf = &bh[ni >> 1][(ni & 1) * 2];
                    const uint32_t* blf = &bl[ni >> 1][(ni & 1) * 2];
                    mma16816(acc[mi][ni], ah[mi], bhf);
                    mma16816(acc[mi][ni], ah[mi], blf);
                    mma16816(acc[mi][ni], al[mi], bhf);
                }
        }
        __syncthreads();
    }

    /* epilogue: store tanh(D + b) matrix (float2 per fragment half) */
#pragma unroll
    for (int mi = 0; mi < 2; mi++)
#pragma unroll
        for (int ni = 0; ni < 8; ni++) {
            int c0 = n_base + ni * 8 + (lane & 3) * 2;
            int r0 = m_base + mi * 16 + (lane >> 2);
            float2 v0, v1;
            v0.x = tanh_acc(acc[mi][ni][0] + bss[c0]);
            v0.y = tanh_acc(acc[mi][ni][1] + bss[c0 + 1]);
            v1.x = tanh_acc(acc[mi][ni][2] + bss[c0]);
            v1.y = tanh_acc(acc[mi][ni][3] + bss[c0 + 1]);
            *(float2*)&g_tanh[(size_t)(bm0 + r0) * Hdim + bn0 + c0]     = v0;
            *(float2*)&g_tanh[(size_t)(bm0 + r0 + 8) * Hdim + bn0 + c0] = v1;
        }
}

/* --------- K9b: score_c = g_tanh @ h1 (warp per row) ---------------------- */
__global__ void k_scdot(float* __restrict__ out) {
    __shared__ float4 hv[256];
    int t = threadIdx.x;
    if (t < 256) hv[t] = ((const float4*)g_h1)[t];
    __syncthreads();
    int warp = t >> 5, lane = t & 31;
    int row = blockIdx.x * 8 + warp;
    const float4* Tr = (const float4*)(g_tanh + (size_t)row * Hdim);
    float acc = 0.f;
#pragma unroll
    for (int i = 0; i < 8; i++) {
        int f = lane + i * 32;
        acc += dot4(Tr[f], hv[f]);
    }
    acc = warp_red(acc);
    if (lane == 0) out[Vv + row] = acc;
}

/* --------- K10: final softmax over 52305 scores --------------------------- */
__global__ void k_softmax_out(float* __restrict__ out) {
    int t = threadIdx.x;
    __shared__ float red[1024];
    float m = -1e30f;
    for (int i = t; i < PROBN; i += 1024) m = fmaxf(m, out[i]);
    red[t] = m; __syncthreads();
    for (int s = 512; s > 0; s >>= 1) { if (t < s) red[t] = fmaxf(red[t], red[t + s]); __syncthreads(); }
    m = red[0]; __syncthreads();
    float sum = 0.f;
    for (int i = t; i < PROBN; i += 1024) sum += __expf(out[i] - m);
    red[t] = sum; __syncthreads();
    for (int s = 512; s > 0; s >>= 1) { if (t < s) red[t] += red[t + s]; __syncthreads(); }
    float inv = 1.0f / red[0];
    for (int i = t; i < PROBN; i += 1024) out[i] = __expf(out[i] - m) * inv;
}

/* ------------------------- launcher --------------------------------------- */
extern "C" void kernel_launch(void* const* d_in, const int* in_sizes, int n_in,
                              void* d_out, int out_size) {
    const float* x          = (const float*)d_in[0];
    const float* enc        = (const float*)d_in[1];
    const int*   sent       = (const int*)  d_in[2];
    const float* prev_probs = (const float*)d_in[3];
    const float* h0         = (const float*)d_in[4];
    const float* c0         = (const float*)d_in[5];
    const float* attn_W     = (const float*)d_in[6];
    const float* attn_b     = (const float*)d_in[7];
    const float* comb_W     = (const float*)d_in[8];
    const float* comb_b     = (const float*)d_in[9];
    const float* Ws_W       = (const float*)d_in[10];
    const float* Ws_b       = (const float*)d_in[11];
    const float* Wo_W       = (const float*)d_in[12];
    const float* Wo_b       = (const float*)d_in[13];
    const float* Wc_W       = (const float*)d_in[14];
    const float* Wc_b       = (const float*)d_in[15];
    const float* W_ih       = (const float*)d_in[16];
    const float* W_hh       = (const float*)d_in[17];
    const float* b_ih       = (const float*)d_in[18];
    const float* b_hh       = (const float*)d_in[19];
    const int*   pw         = (const int*)  d_in[20];
    float* out = (float*)d_out;

    cudaFuncSetAttribute(k_scorec_mma, cudaFuncAttributeMaxDynamicSharedMemorySize,
                         NPIPE * STAGE_SB);

    static cudaStream_t s1 = 0, s2 = 0;
    static cudaEvent_t e0 = 0, e2 = 0, eL = 0, eS = 0;
    static int use_streams = -1;
    if (use_streams < 0) {
        if (cudaStreamCreateWithFlags(&s1, cudaStreamNonBlocking) == cudaSuccess &&
            cudaStreamCreateWithFlags(&s2, cudaStreamNonBlocking) == cudaSuccess &&
            cudaEventCreateWithFlags(&e0, cudaEventDisableTiming) == cudaSuccess &&
            cudaEventCreateWithFlags(&e2, cudaEventDisableTiming) == cudaSuccess &&
            cudaEventCreateWithFlags(&eL, cudaEventDisableTiming) == cudaSuccess &&
            cudaEventCreateWithFlags(&eS, cudaEventDisableTiming) == cudaSuccess)
            use_streams = 1;
        else
            use_streams = 0;
    }

    if (use_streams) {
        /* fork */
        cudaEventRecord(e0, 0);
        cudaStreamWaitEvent(s1, e0, 0);
        cudaStreamWaitEvent(s2, e0, 0);

        /* s1: conversions + h1-free tanh GEMM (overlaps entire LSTM chain) */
        k_cvt_enc<<<4096, 256, 0, s1>>>((const float4*)enc);
        k_cvt_wc<<<2048, 256, 0, s1>>>((const float4*)Wc_W);
        k_scorec_mma<<<dim3(16, 8), 256, NPIPE * STAGE_SB, s1>>>(Wc_b);

        /* s2: gate pre-part */
        k_gates_pre<<<512, 256, 0, s2>>>(x, h0, W_ih, W_hh, b_ih, b_hh);
        cudaEventRecord(e2, s2);

        /* main chain to h1 */
        k_attn<<<256, 256>>>(x, h0, attn_W, attn_b);
        k_rho_softmax<<<1, 256>>>(sent, prev_probs, pw);
        k_colred<<<dim3(8, 64), 256>>>(enc);
        k_colfin<<<8, 256>>>();
        k_combws<<<256, 256>>>(comb_W, comb_b, Ws_W, Ws_b);
        cudaStreamWaitEvent(0, e2, 0);
        k_gates_post<<<512, 256>>>(W_ih);
        k_lstm<<<4, 256>>>(c0, out);
        cudaEventRecord(eL, 0);

        /* s1: score_c dot (needs h1 + tanh matrix), overlaps k_wo */
        cudaStreamWaitEvent(s1, eL, 0);
        k_scdot<<<256, 256, 0, s1>>>(out);
        cudaEventRecord(eS, s1);

        /* main: vocab GEMV then join + softmax */
        k_wo<<<(Vv + 7) / 8, 256>>>(Wo_W, Wo_b, out);
        cudaStreamWaitEvent(0, eS, 0);
        k_softmax_out<<<1, 1024>>>(out);
    } else {
        k_cvt_enc<<<4096, 256>>>((const float4*)enc);
        k_cvt_wc<<<2048, 256>>>((const float4*)Wc_W);
        k_scorec_mma<<<dim3(16, 8), 256, NPIPE * STAGE_SB>>>(Wc_b);
        k_gates_pre<<<512, 256>>>(x, h0, W_ih, W_hh, b_ih, b_hh);
        k_attn<<<256, 256>>>(x, h0, attn_W, attn_b);
        k_rho_softmax<<<1, 256>>>(sent, prev_probs, pw);
        k_colred<<<dim3(8, 64), 256>>>(enc);
        k_colfin<<<8, 256>>>();
        k_combws<<<256, 256>>>(comb_W, comb_b, Ws_W, Ws_b);
        k_gates_post<<<512, 256>>>(W_ih);
        k_lstm<<<4, 256>>>(c0, out);
        k_scdot<<<256, 256>>>(out);
        k_wo<<<(Vv + 7) / 8, 256>>>(Wo_W, Wo_b, out);
        k_softmax_out<<<1, 1024>>>(out);
    }
}

// round 7
// speedup vs baseline: 3.8212x; 1.1445x over previous
#include <cuda_runtime.h>
#include <cuda_bf16.h>
#include <math.h>
#include <stdint.h>

#define Vv     50257
#define Sdim   2048
#define Hdim   1024
#define H2     2048
#define IN3    3072
#define G4     4096
#define PROBN  (Vv + Sdim)   /* 52305 */

/* ------------------------- device scratch (no allocs) ------------------- */
__device__ float g_logits[Sdim];
__device__ float g_rho[Sdim];
__device__ float g_colpart[64][2][H2];
__device__ float g_ctx[H2];
__device__ float g_rhoenc[H2];
__device__ float g_lstm_in[IN3];
__device__ float g_gates[G4];
__device__ float g_h1[Hdim];
__device__ float g_c1[Hdim];
__device__ float g_tanh[(size_t)Sdim * Hdim];   /* tanh(enc@Wc.T+b) matrix */

/* ------------------------- math helpers (fast-math safe) ---------------- */
__device__ __forceinline__ float sigmoid_acc(float x) {
    return 1.0f / (1.0f + expf(-x));
}
__device__ __forceinline__ float tanh_acc(float x) {
    return 1.0f - 2.0f / (expf(2.0f * x) + 1.0f);
}
__device__ __forceinline__ float dot4(float4 a, float4 b) {
    return a.x * b.x + a.y * b.y + a.z * b.z + a.w * b.w;
}
__device__ __forceinline__ float warp_red(float v) {
#pragma unroll
    for (int s = 16; s > 0; s >>= 1) v += __shfl_down_sync(0xffffffffu, v, s);
    return v;
}

__device__ __forceinline__ uint32_t smem_u32(const void* p) {
    uint32_t a;
    asm("{ .reg .u64 t; cvta.to.shared.u64 t, %1; cvt.u32.u64 %0, t; }" : "=r"(a) : "l"(p));
    return a;
}

__device__ __forceinline__ void mma16816(float* c, const uint32_t* a, const uint32_t* b) {
    asm volatile(
        "mma.sync.aligned.m16n8k16.row.col.f32.bf16.bf16.f32 "
        "{%0,%1,%2,%3}, {%4,%5,%6,%7}, {%8,%9}, {%0,%1,%2,%3};"
        : "+f"(c[0]), "+f"(c[1]), "+f"(c[2]), "+f"(c[3])
        : "r"(a[0]), "r"(a[1]), "r"(a[2]), "r"(a[3]), "r"(b[0]), "r"(b[1]));
}
__device__ __forceinline__ void ldmx4(uint32_t* r, uint32_t addr) {
    asm volatile("ldmatrix.sync.aligned.m8n8.x4.shared.b16 {%0,%1,%2,%3}, [%4];"
        : "=r"(r[0]), "=r"(r[1]), "=r"(r[2]), "=r"(r[3]) : "r"(addr));
}
__device__ __forceinline__ uint32_t packhi(float a, float b) {
    __nv_bfloat162 h = __halves2bfloat162(__float2bfloat16(a), __float2bfloat16(b));
    return *(uint32_t*)&h;
}
__device__ __forceinline__ uint32_t packlo(float a, float b) {
    float ra = a - __bfloat162float(__float2bfloat16(a));
    float rb = b - __bfloat162float(__float2bfloat16(b));
    __nv_bfloat162 h = __halves2bfloat162(__float2bfloat16(ra), __float2bfloat16(rb));
    return *(uint32_t*)&h;
}

/* ------------- K1: attention logits GEMV (warp per row, 8 rows/blk) ------ */
__global__ void k_attn(const float* __restrict__ x, const float* __restrict__ h0,
                       const float* __restrict__ W, const float* __restrict__ b) {
    __shared__ float4 vec[512];
    int t = threadIdx.x;
    if (t < 256) { vec[t] = ((const float4*)x)[t]; vec[t + 256] = ((const float4*)h0)[t]; }
    __syncthreads();
    int warp = t >> 5, lane = t & 31;
    int row = blockIdx.x * 8 + warp;
    const float4* Wr = (const float4*)(W + (size_t)row * H2);
    float acc = 0.f;
#pragma unroll
    for (int i = 0; i < 16; i++) {
        int f = lane + i * 32;
        acc += dot4(Wr[f], vec[f]);
    }
    acc = warp_red(acc);
    if (lane == 0) g_logits[row] = acc + b[row];
}

/* --------------- K2: rho mask+normalize fused with attn softmax ---------- */
__global__ void k_rho_softmax(const int* __restrict__ sent, const float* __restrict__ prev_probs,
                              const int* __restrict__ pw) {
    int t = threadIdx.x;
    __shared__ float red[256];
    {
        int w = pw[0];
        float vals[8];
        float part = 0.f;
#pragma unroll
        for (int i = 0; i < 8; i++) {
            int s = t + i * 256;
            float v = (sent[s] == w) ? prev_probs[Vv + s] : 0.f;
            vals[i] = v; part += v;
        }
        red[t] = part; __syncthreads();
        for (int s = 128; s > 0; s >>= 1) { if (t < s) red[t] += red[t + s]; __syncthreads(); }
        float inv = 1.0f / (red[0] + 1e-9f);
#pragma unroll
        for (int i = 0; i < 8; i++) g_rho[t + i * 256] = vals[i] * inv;
        __syncthreads();
    }
    {
        float vals[8];
        float m = -1e30f;
#pragma unroll
        for (int i = 0; i < 8; i++) { vals[i] = g_logits[t + i * 256]; m = fmaxf(m, vals[i]); }
        red[t] = m; __syncthreads();
        for (int s = 128; s > 0; s >>= 1) { if (t < s) red[t] = fmaxf(red[t], red[t + s]); __syncthreads(); }
        m = red[0]; __syncthreads();
        float sum = 0.f;
#pragma unroll
        for (int i = 0; i < 8; i++) { vals[i] = __expf(vals[i] - m); sum += vals[i]; }
        red[t] = sum; __syncthreads();
        for (int s = 128; s > 0; s >>= 1) { if (t < s) red[t] += red[t + s]; __syncthreads(); }
        float inv = 1.0f / red[0];
#pragma unroll
        for (int i = 0; i < 8; i++) g_logits[t + i * 256] = vals[i] * inv;
    }
}

/* --------- K4: fused column reductions ctx & rho@enc over encoder -------- */
__global__ void k_colred(const float* __restrict__ enc) {
    int t   = threadIdx.x;
    int col = blockIdx.x * 256 + t;
    int rc  = blockIdx.y;               // 64 row chunks of 32
    __shared__ float aw[32], rw[32];
    if (t < 32) aw[t] = g_logits[rc * 32 + t];
    else if (t < 64) rw[t - 32] = g_rho[rc * 32 + (t - 32)];
    __syncthreads();
    float a = 0.f, r = 0.f;
    const float* base = enc + (size_t)(rc * 32) * H2 + col;
#pragma unroll
    for (int i = 0; i < 32; i++) {
        float v = base[(size_t)i * H2];
        a += aw[i] * v;
        r += rw[i] * v;
    }
    g_colpart[rc][0][col] = a;
    g_colpart[rc][1][col] = r;
}

__global__ void k_colfin() {
    int col = blockIdx.x * 256 + threadIdx.x;
    float a = 0.f, r = 0.f;
#pragma unroll
    for (int c = 0; c < 64; c++) { a += g_colpart[c][0][col]; r += g_colpart[c][1][col]; }
    g_ctx[col] = a;
    g_rhoenc[col] = r;
}

/* -------- K5: attentive & selective GEMVs (warp per row, 8/blk) ---------- */
__global__ void k_combws(const float* __restrict__ combW, const float* __restrict__ combb,
                         const float* __restrict__ WsW,  const float* __restrict__ Wsb) {
    __shared__ float4 vec[512];
    int t = threadIdx.x;
    bool isComb = blockIdx.x < 128;
    const float4* v4 = isComb ? (const float4*)g_ctx : (const float4*)g_rhoenc;
    if (t < 256) { vec[t] = v4[t]; vec[t + 256] = v4[t + 256]; }
    __syncthreads();
    int warp = t >> 5, lane = t & 31;
    int row = blockIdx.x * 8 + warp;     /* 0..2047 */
    int lrow = isComb ? row : row - Hdim;
    const float4* Wr = isComb ? (const float4*)(combW + (size_t)lrow * H2)
                              : (const float4*)(WsW + (size_t)lrow * H2);
    float acc = 0.f;
#pragma unroll
    for (int i = 0; i < 16; i++) {
        int f = lane + i * 32;
        acc += dot4(Wr[f], vec[f]);
    }
    acc = warp_red(acc);
    if (lane == 0) {
        if (isComb) g_lstm_in[2 * Hdim + lrow] = acc + combb[lrow];
        else        g_lstm_in[Hdim + lrow] = acc + Wsb[lrow];
    }
}

/* --------- K6a: gate GEMV pre-part (x + h0 terms; warp per row) ---------- */
__global__ void k_gates_pre(const float* __restrict__ x, const float* __restrict__ h0,
                            const float* __restrict__ Wih, const float* __restrict__ Whh,
                            const float* __restrict__ bih, const float* __restrict__ bhh) {
    __shared__ float4 vx[256], vh[256];
    int t = threadIdx.x;
    if (t < 256) { vx[t] = ((const float4*)x)[t]; vh[t] = ((const float4*)h0)[t]; }
    __syncthreads();
    int warp = t >> 5, lane = t & 31;
    int row = blockIdx.x * 8 + warp;     /* 0..4095 */
    const float4* Wi = (const float4*)(Wih + (size_t)row * IN3);
    const float4* Wh = (const float4*)(Whh + (size_t)row * Hdim);
    float acc = 0.f;
#pragma unroll
    for (int i = 0; i < 8; i++) {
        int f = lane + i * 32;
        acc += dot4(Wi[f], vx[f]);
        acc += dot4(Wh[f], vh[f]);
    }
    acc = warp_red(acc);
    if (lane == 0) g_gates[row] = acc + bih[row] + bhh[row];
}

/* --------- K6b: gate GEMV post-part (selective+attentive; warp/row) ------ */
__global__ void k_gates_post(const float* __restrict__ Wih) {
    __shared__ float4 vec[512];
    int t = threadIdx.x;
    const float4* li = (const float4*)(g_lstm_in + Hdim);
    if (t < 256) { vec[t] = li[t]; vec[t + 256] = li[t + 256]; }
    __syncthreads();
    int warp = t >> 5, lane = t & 31;
    int row = blockIdx.x * 8 + warp;
    const float4* Wi = (const float4*)(Wih + (size_t)row * IN3 + Hdim);
    float acc = 0.f;
#pragma unroll
    for (int i = 0; i < 16; i++) {
        int f = lane + i * 32;
        acc += dot4(Wi[f], vec[f]);
    }
    acc = warp_red(acc);
    if (lane == 0) g_gates[row] += acc;
}

/* --------- K7: LSTM elementwise ------------------------------------------ */
__global__ void k_lstm(const float* __restrict__ c0, float* __restrict__ out) {
    int i = blockIdx.x * 256 + threadIdx.x;
    float gi = g_gates[i];
    float gf = g_gates[Hdim + i];
    float gg = g_gates[2 * Hdim + i];
    float go = g_gates[3 * Hdim + i];
    float c1 = sigmoid_acc(gf) * c0[i] + sigmoid_acc(gi) * tanh_acc(gg);
    float h1 = sigmoid_acc(go) * tanh_acc(c1);
    g_c1[i] = c1; g_h1[i] = h1;
    out[PROBN + i] = h1;
    out[PROBN + Hdim + i] = c1;
}

/* --------- K8: vocab GEMV score_g = h1 @ Wo.T + b (warp per row) ---------- */
__global__ void k_wo(const float* __restrict__ Wo, const float* __restrict__ Wob,
                     float* __restrict__ out) {
    __shared__ float h1s[Hdim];
    int t = threadIdx.x;
    for (int i = t; i < Hdim; i += 256) h1s[i] = g_h1[i];
    __syncthreads();
    int warp = t >> 5, lane = t & 31;
    int row = blockIdx.x * 8 + warp;
    if (row >= Vv) return;
    const float4* Wr = (const float4*)(Wo + (size_t)row * Hdim);
    const float4* hv = (const float4*)h1s;
    float acc = 0.f;
#pragma unroll
    for (int i = 0; i < 8; i++) {
        int f = lane + i * 32;
        acc += dot4(Wr[f], hv[f]);
    }
    acc = warp_red(acc);
    if (lane == 0) out[row] = acc + Wob[row];
}

/* --------- K9: tanh(enc@Wc.T+b) via mma.sync with in-kernel fp32 split --- */
/* Loads fp32 enc/Wc directly, converts to bf16 hi/lo in registers, stores  */
/* to smem. 3-term split GEMM. h1-independent: starts at t=0.               */
#define KC 32
#define ROWB 80                       /* 40 bf16 padded row = 80 bytes */
#define TILE_SB (128 * ROWB)          /* 10240 B per tile */
#define STAGE_SB (4 * TILE_SB)        /* 40960 B per stage (Ahi,Alo,Bhi,Blo) */
#define NBUF 3
#define NSTAGES (H2 / KC)             /* 64 */

__global__ __launch_bounds__(256, 1)
void k_scorec_mma(const float* __restrict__ enc, const float* __restrict__ Wc,
                  const float* __restrict__ Wcb) {
    extern __shared__ char dynsm[];
    __shared__ float bss[128];

    const int tid = threadIdx.x;
    const int wid = tid >> 5, lane = tid & 31;
    const int warpM = wid & 3, warpN = wid >> 2;
    const int m_base = warpM * 32;
    const int n_base = warpN * 64;
    const int bm0 = blockIdx.x * 128;
    const int bn0 = blockIdx.y * 128;

    const uint32_t smbase = smem_u32(dynsm);

    if (tid < 128) bss[tid] = Wcb[bn0 + tid];

    /* loader mapping: thread t -> row r = t>>1, half h = t&1 (16 floats) */
    const int lr = tid >> 1;
    const int lh = tid & 1;
    const float4* gA = (const float4*)(enc + (size_t)(bm0 + lr) * H2) + lh * 4;
    const float4* gB = (const float4*)(Wc  + (size_t)(bn0 + lr) * H2) + lh * 4;

    float4 ra[4], rb[4];

#define LOAD_REGS(CH) do {                                                     \
        int kf4 = (CH) * (KC / 4);                                             \
        _Pragma("unroll")                                                      \
        for (int i = 0; i < 4; i++) { ra[i] = gA[kf4 + i]; rb[i] = gB[kf4 + i]; } \
    } while (0)

#define STORE_REGS(CH) do {                                                    \
        char* stage = dynsm + ((CH) % NBUF) * STAGE_SB;                        \
        uint32_t hi[8], lo[8];                                                 \
        _Pragma("unroll")                                                      \
        for (int i = 0; i < 4; i++) {                                          \
            hi[2*i]   = packhi(ra[i].x, ra[i].y);                              \
            hi[2*i+1] = packhi(ra[i].z, ra[i].w);                              \
            lo[2*i]   = packlo(ra[i].x, ra[i].y);                              \
            lo[2*i+1] = packlo(ra[i].z, ra[i].w);                              \
        }                                                                      \
        *(uint4*)(stage + 0 * TILE_SB + lr * ROWB + lh * 32)      = make_uint4(hi[0],hi[1],hi[2],hi[3]); \
        *(uint4*)(stage + 0 * TILE_SB + lr * ROWB + lh * 32 + 16) = make_uint4(hi[4],hi[5],hi[6],hi[7]); \
        *(uint4*)(stage + 1 * TILE_SB + lr * ROWB + lh * 32)      = make_uint4(lo[0],lo[1],lo[2],lo[3]); \
        *(uint4*)(stage + 1 * TILE_SB + lr * ROWB + lh * 32 + 16) = make_uint4(lo[4],lo[5],lo[6],lo[7]); \
        _Pragma("unroll")                                                      \
        for (int i = 0; i < 4; i++) {                                          \
            hi[2*i]   = packhi(rb[i].x, rb[i].y);                              \
            hi[2*i+1] = packhi(rb[i].z, rb[i].w);                              \
            lo[2*i]   = packlo(rb[i].x, rb[i].y);                              \
            lo[2*i+1] = packlo(rb[i].z, rb[i].w);                              \
        }                                                                      \
        *(uint4*)(stage + 2 * TILE_SB + lr * ROWB + lh * 32)      = make_uint4(hi[0],hi[1],hi[2],hi[3]); \
        *(uint4*)(stage + 2 * TILE_SB + lr * ROWB + lh * 32 + 16) = make_uint4(hi[4],hi[5],hi[6],hi[7]); \
        *(uint4*)(stage + 3 * TILE_SB + lr * ROWB + lh * 32)      = make_uint4(lo[0],lo[1],lo[2],lo[3]); \
        *(uint4*)(stage + 3 * TILE_SB + lr * ROWB + lh * 32 + 16) = make_uint4(lo[4],lo[5],lo[6],lo[7]); \
    } while (0)

    float acc[2][8][4];
#pragma unroll
    for (int mi = 0; mi < 2; mi++)
#pragma unroll
        for (int ni = 0; ni < 8; ni++)
#pragma unroll
            for (int r = 0; r < 4; r++) acc[mi][ni][r] = 0.f;

    /* prologue: fill buffers 0 and 1 */
    LOAD_REGS(0); STORE_REGS(0);
    LOAD_REGS(1); STORE_REGS(1);
    __syncthreads();

    for (int ch = 0; ch < NSTAGES; ch++) {
        if (ch + 2 < NSTAGES) LOAD_REGS(ch + 2);

        const uint32_t sb = smbase + (ch % NBUF) * STAGE_SB;
        const uint32_t ah_b = sb + 0 * TILE_SB;
        const uint32_t bh_b = sb + 2 * TILE_SB;

#pragma unroll
        for (int s = 0; s < 2; s++) {           /* two k16 slices per stage */
            const int ks4 = s * 32;             /* byte offset of slice */
            uint32_t ah[2][4], al[2][4], bh[4][4], bl[4][4];
#pragma unroll
            for (int mi = 0; mi < 2; mi++) {
                uint32_t row = m_base + mi * 16 + (lane & 15);
                uint32_t addr = ah_b + row * ROWB + ks4 + ((lane >> 4) << 4);
                ldmx4(ah[mi], addr);
                ldmx4(al[mi], addr + TILE_SB);
            }
#pragma unroll
            for (int p = 0; p < 4; p++) {
                uint32_t row = n_base + p * 16 + ((lane >> 4) << 3) + (lane & 7);
                uint32_t addr = bh_b + row * ROWB + ks4 + (((lane >> 3) & 1) << 4);
                ldmx4(bh[p], addr);
                ldmx4(bl[p], addr + TILE_SB);
            }
#pragma unroll
            for (int mi = 0; mi < 2; mi++)
#pragma unroll
                for (int ni = 0; ni < 8; ni++) {
                    const uint32_t* bhf = &bh[ni >> 1][(ni & 1) * 2];
                    const uint32_t* blf = &bl[ni >> 1][(ni & 1) * 2];
                    mma16816(acc[mi][ni], ah[mi], bhf);
                    mma16816(acc[mi][ni], ah[mi], blf);
                    mma16816(acc[mi][ni], al[mi], bhf);
                }
        }
        if (ch + 2 < NSTAGES) STORE_REGS(ch + 2);
        __syncthreads();
    }

    /* epilogue: store tanh(D + b) matrix (float2 per fragment half) */
#pragma unroll
    for (int mi = 0; mi < 2; mi++)
#pragma unroll
        for (int ni = 0; ni < 8; ni++) {
            int c0 = n_base + ni * 8 + (lane & 3) * 2;
            int r0 = m_base + mi * 16 + (lane >> 2);
            float2 v0, v1;
            v0.x = tanh_acc(acc[mi][ni][0] + bss[c0]);
            v0.y = tanh_acc(acc[mi][ni][1] + bss[c0 + 1]);
            v1.x = tanh_acc(acc[mi][ni][2] + bss[c0]);
            v1.y = tanh_acc(acc[mi][ni][3] + bss[c0 + 1]);
            *(float2*)&g_tanh[(size_t)(bm0 + r0) * Hdim + bn0 + c0]     = v0;
            *(float2*)&g_tanh[(size_t)(bm0 + r0 + 8) * Hdim + bn0 + c0] = v1;
        }
}

/* --------- K9b: score_c = g_tanh @ h1 (warp per row) ---------------------- */
__global__ void k_scdot(float* __restrict__ out) {
    __shared__ float4 hv[256];
    int t = threadIdx.x;
    if (t < 256) hv[t] = ((const float4*)g_h1)[t];
    __syncthreads();
    int warp = t >> 5, lane = t & 31;
    int row = blockIdx.x * 8 + warp;
    const float4* Tr = (const float4*)(g_tanh + (size_t)row * Hdim);
    float acc = 0.f;
#pragma unroll
    for (int i = 0; i < 8; i++) {
        int f = lane + i * 32;
        acc += dot4(Tr[f], hv[f]);
    }
    acc = warp_red(acc);
    if (lane == 0) out[Vv + row] = acc;
}

/* --------- K10: final softmax over 52305 scores --------------------------- */
__global__ void k_softmax_out(float* __restrict__ out) {
    int t = threadIdx.x;
    __shared__ float red[1024];
    float m = -1e30f;
    for (int i = t; i < PROBN; i += 1024) m = fmaxf(m, out[i]);
    red[t] = m; __syncthreads();
    for (int s = 512; s > 0; s >>= 1) { if (t < s) red[t] = fmaxf(red[t], red[t + s]); __syncthreads(); }
    m = red[0]; __syncthreads();
    float sum = 0.f;
    for (int i = t; i < PROBN; i += 1024) sum += __expf(out[i] - m);
    red[t] = sum; __syncthreads();
    for (int s = 512; s > 0; s >>= 1) { if (t < s) red[t] += red[t + s]; __syncthreads(); }
    float inv = 1.0f / red[0];
    for (int i = t; i < PROBN; i += 1024) out[i] = __expf(out[i] - m) * inv;
}

/* ------------------------- launcher --------------------------------------- */
extern "C" void kernel_launch(void* const* d_in, const int* in_sizes, int n_in,
                              void* d_out, int out_size) {
    const float* x          = (const float*)d_in[0];
    const float* enc        = (const float*)d_in[1];
    const int*   sent       = (const int*)  d_in[2];
    const float* prev_probs = (const float*)d_in[3];
    const float* h0         = (const float*)d_in[4];
    const float* c0         = (const float*)d_in[5];
    const float* attn_W     = (const float*)d_in[6];
    const float* attn_b     = (const float*)d_in[7];
    const float* comb_W     = (const float*)d_in[8];
    const float* comb_b     = (const float*)d_in[9];
    const float* Ws_W       = (const float*)d_in[10];
    const float* Ws_b       = (const float*)d_in[11];
    const float* Wo_W       = (const float*)d_in[12];
    const float* Wo_b       = (const float*)d_in[13];
    const float* Wc_W       = (const float*)d_in[14];
    const float* Wc_b       = (const float*)d_in[15];
    const float* W_ih       = (const float*)d_in[16];
    const float* W_hh       = (const float*)d_in[17];
    const float* b_ih       = (const float*)d_in[18];
    const float* b_hh       = (const float*)d_in[19];
    const int*   pw         = (const int*)  d_in[20];
    float* out = (float*)d_out;

    cudaFuncSetAttribute(k_scorec_mma, cudaFuncAttributeMaxDynamicSharedMemorySize,
                         NBUF * STAGE_SB);

    static cudaStream_t s1 = 0, s2 = 0;
    static cudaEvent_t e0 = 0, e2 = 0, eL = 0, eS = 0;
    static int use_streams = -1;
    if (use_streams < 0) {
        if (cudaStreamCreateWithFlags(&s1, cudaStreamNonBlocking) == cudaSuccess &&
            cudaStreamCreateWithFlags(&s2, cudaStreamNonBlocking) == cudaSuccess &&
            cudaEventCreateWithFlags(&e0, cudaEventDisableTiming) == cudaSuccess &&
            cudaEventCreateWithFlags(&e2, cudaEventDisableTiming) == cudaSuccess &&
            cudaEventCreateWithFlags(&eL, cudaEventDisableTiming) == cudaSuccess &&
            cudaEventCreateWithFlags(&eS, cudaEventDisableTiming) == cudaSuccess)
            use_streams = 1;
        else
            use_streams = 0;
    }

    if (use_streams) {
        /* fork */
        cudaEventRecord(e0, 0);
        cudaStreamWaitEvent(s1, e0, 0);
        cudaStreamWaitEvent(s2, e0, 0);

        /* s1: h1-free tanh GEMM with fused fp32 split (starts at t=0) */
        k_scorec_mma<<<dim3(16, 8), 256, NBUF * STAGE_SB, s1>>>(enc, Wc_W, Wc_b);

        /* s2: gate pre-part */
        k_gates_pre<<<512, 256, 0, s2>>>(x, h0, W_ih, W_hh, b_ih, b_hh);
        cudaEventRecord(e2, s2);

        /* main chain to h1 */
        k_attn<<<256, 256>>>(x, h0, attn_W, attn_b);
        k_rho_softmax<<<1, 256>>>(sent, prev_probs, pw);
        k_colred<<<dim3(8, 64), 256>>>(enc);
        k_colfin<<<8, 256>>>();
        k_combws<<<256, 256>>>(comb_W, comb_b, Ws_W, Ws_b);
        cudaStreamWaitEvent(0, e2, 0);
        k_gates_post<<<512, 256>>>(W_ih);
        k_lstm<<<4, 256>>>(c0, out);
        cudaEventRecord(eL, 0);

        /* s1: score_c dot (needs h1 + tanh matrix), overlaps k_wo */
        cudaStreamWaitEvent(s1, eL, 0);
        k_scdot<<<256, 256, 0, s1>>>(out);
        cudaEventRecord(eS, s1);

        /* main: vocab GEMV then join + softmax */
        k_wo<<<(Vv + 7) / 8, 256>>>(Wo_W, Wo_b, out);
        cudaStreamWaitEvent(0, eS, 0);
        k_softmax_out<<<1, 1024>>>(out);
    } else {
        k_scorec_mma<<<dim3(16, 8), 256, NBUF * STAGE_SB>>>(enc, Wc_W, Wc_b);
        k_gates_pre<<<512, 256>>>(x, h0, W_ih, W_hh, b_ih, b_hh);
        k_attn<<<256, 256>>>(x, h0, attn_W, attn_b);
        k_rho_softmax<<<1, 256>>>(sent, prev_probs, pw);
        k_colred<<<dim3(8, 64), 256>>>(enc);
        k_colfin<<<8, 256>>>();
        k_combws<<<256, 256>>>(comb_W, comb_b, Ws_W, Ws_b);
        k_gates_post<<<512, 256>>>(W_ih);
        k_lstm<<<4, 256>>>(c0, out);
        k_scdot<<<256, 256>>>(out);
        k_wo<<<(Vv + 7) / 8, 256>>>(Wo_W, Wo_b, out);
        k_softmax_out<<<1, 1024>>>(out);
    }
}